// round 1
// baseline (speedup 1.0000x reference)
#include <cuda_runtime.h>
#include <stdint.h>

#define D 128
#define NMAX 100000

// Scratch: per-node projections A = z @ W1[:128], B = z @ W1[128:] + b1
__device__ float g_A[(size_t)NMAX * D];
__device__ float g_B[(size_t)NMAX * D];
__device__ int g_is64;

// ---------------------------------------------------------------------------
// Detect whether edge_index buffer is int64 or int32 (JAX may demote to i32).
// If the data is really int32, reinterpreting as int64 packs two random
// indices into one value, which is >= 2^32 with overwhelming probability.
// ---------------------------------------------------------------------------
__global__ void detect_idx_kernel(const long long* __restrict__ ei, int N) {
    if (threadIdx.x == 0) {
        int ok = 1;
#pragma unroll
        for (int i = 0; i < 8; i++) {
            long long v = ei[i];
            if (v < 0 || v >= (long long)N) ok = 0;
        }
        g_is64 = ok;
    }
}

// ---------------------------------------------------------------------------
// Node projection GEMM:  [N,128] @ [128,256] -> A[N,128], B[N,128](+b1)
//   A[n,d] = sum_k z[n,k] * W1[k,d]
//   B[n,d] = sum_k z[n,k] * W1[128+k,d] + b1[d]
// Tile: BM=128 rows x 256 cols, full K=128 in one shot.
// 512 threads, 8x8 register microtile each. Smem: W1 copy (128KB) + z^T (64KB).
// ---------------------------------------------------------------------------
__global__ void __launch_bounds__(512, 1)
node_proj_kernel(const float* __restrict__ z, const float* __restrict__ W1,
                 const float* __restrict__ b1, int N)
{
    extern __shared__ float smem[];
    float* ws = smem;            // 32768 floats: straight copy of W1 [256][128]
    float* zs = smem + 32768;    // 16384 floats: z^T tile, zs[k][m], m in [0,128)

    const int tid = threadIdx.x;
    const int m0 = blockIdx.x * 128;

    // Load W1 (128 KB) cooperatively, vectorized.
    {
        const float4* w4 = (const float4*)W1;
        float4* ws4 = (float4*)ws;
#pragma unroll
        for (int i = tid; i < 8192; i += 512) ws4[i] = w4[i];
    }

    // Load z tile transposed into zs[k][m]. i = k4*128 + m so consecutive
    // threads write consecutive m -> conflict-free smem stores.
#pragma unroll
    for (int it = 0; it < 8; it++) {
        int i = tid + it * 512;            // [0, 4096)
        int k4 = i >> 7;                   // which float4 along k
        int m  = i & 127;                  // row within tile
        float4 v = make_float4(0.f, 0.f, 0.f, 0.f);
        if (m0 + m < N)
            v = ((const float4*)z)[(size_t)(m0 + m) * 32 + k4];
        zs[(k4 * 4 + 0) * 128 + m] = v.x;
        zs[(k4 * 4 + 1) * 128 + m] = v.y;
        zs[(k4 * 4 + 2) * 128 + m] = v.z;
        zs[(k4 * 4 + 3) * 128 + m] = v.w;
    }
    __syncthreads();

    const int tcol = tid & 31;       // 32 col-groups of 8 cols (256 total cols)
    const int trow = tid >> 5;       // 16 row-groups of 8 rows (128 rows)
    const int jc   = tcol * 8;       // output col base in [0,256)
    const int regn = jc >> 7;        // 0 -> A half, 1 -> B half
    const int c    = jc & 127;       // col within half

    const float* wbase = ws + regn * 16384 + c;   // ws[(regn*128 + k)*128 + c]
    const float* abase = zs + trow * 8;

    float acc[8][8];
#pragma unroll
    for (int i = 0; i < 8; i++)
#pragma unroll
        for (int j = 0; j < 8; j++) acc[i][j] = 0.f;

#pragma unroll 4
    for (int k = 0; k < 128; k++) {
        const float* ap = abase + k * 128;
        const float* wp = wbase + k * 128;
        float4 a0 = *(const float4*)ap;
        float4 a1 = *(const float4*)(ap + 4);
        float4 c0 = *(const float4*)wp;
        float4 c1 = *(const float4*)(wp + 4);
        float a[8] = {a0.x, a0.y, a0.z, a0.w, a1.x, a1.y, a1.z, a1.w};
        float b[8] = {c0.x, c0.y, c0.z, c0.w, c1.x, c1.y, c1.z, c1.w};
#pragma unroll
        for (int i = 0; i < 8; i++)
#pragma unroll
            for (int j = 0; j < 8; j++)
                acc[i][j] = fmaf(a[i], b[j], acc[i][j]);
    }

    // Epilogue: A half stores raw, B half folds in b1.
    float badd[8];
#pragma unroll
    for (int j = 0; j < 8; j++) badd[j] = (regn == 1) ? b1[c + j] : 0.f;
    float* dstbase = (regn == 0) ? g_A : g_B;

#pragma unroll
    for (int i = 0; i < 8; i++) {
        int m = m0 + trow * 8 + i;
        if (m < N) {
            float4 v0, v1;
            v0.x = acc[i][0] + badd[0];
            v0.y = acc[i][1] + badd[1];
            v0.z = acc[i][2] + badd[2];
            v0.w = acc[i][3] + badd[3];
            v1.x = acc[i][4] + badd[4];
            v1.y = acc[i][5] + badd[5];
            v1.z = acc[i][6] + badd[6];
            v1.w = acc[i][7] + badd[7];
            float* dst = dstbase + (size_t)m * 128 + c;
            *(float4*)dst       = v0;
            *(float4*)(dst + 4) = v1;
        }
    }
}

// ---------------------------------------------------------------------------
// Edge pass: out[e] = sum_d relu(A[row[e],d] + B[col[e],d]) * W2[d] + b2
// One warp per edge (grid-stride). Each lane handles 4 of 128 dims via float4.
// W2 (128 floats) held in registers per lane; warp shfl reduction.
// ---------------------------------------------------------------------------
__global__ void __launch_bounds__(256)
edge_kernel(const void* __restrict__ ei_raw,
            const float* __restrict__ W2,
            const float* __restrict__ b2,
            float* __restrict__ out, int E)
{
    const int lane = threadIdx.x & 31;
    const int warp = (blockIdx.x * blockDim.x + threadIdx.x) >> 5;
    const int nwarp = (gridDim.x * blockDim.x) >> 5;

    const float4 w2v = ((const float4*)W2)[lane];
    const float b2v = b2[0];
    const int is64 = g_is64;

    const long long* ei64 = (const long long*)ei_raw;
    const int*       ei32 = (const int*)ei_raw;

    for (int e = warp; e < E; e += nwarp) {
        int row, col;
        if (is64) {
            row = (int)ei64[e];
            col = (int)ei64[E + e];
        } else {
            row = ei32[e];
            col = ei32[E + e];
        }
        float4 av = ((const float4*)(g_A + (size_t)row * 128))[lane];
        float4 bv = ((const float4*)(g_B + (size_t)col * 128))[lane];

        float s = fmaxf(av.x + bv.x, 0.f) * w2v.x
                + fmaxf(av.y + bv.y, 0.f) * w2v.y
                + fmaxf(av.z + bv.z, 0.f) * w2v.z
                + fmaxf(av.w + bv.w, 0.f) * w2v.w;

#pragma unroll
        for (int o = 16; o; o >>= 1)
            s += __shfl_xor_sync(0xffffffffu, s, o);

        if (lane == 0) out[e] = s + b2v;
    }
}

// ---------------------------------------------------------------------------
// Launch
// ---------------------------------------------------------------------------
extern "C" void kernel_launch(void* const* d_in, const int* in_sizes, int n_in,
                              void* d_out, int out_size)
{
    const float* z  = (const float*)d_in[0];
    const void*  ei = d_in[1];
    const float* W1 = (const float*)d_in[2];
    const float* b1 = (const float*)d_in[3];
    const float* W2 = (const float*)d_in[4];
    const float* b2 = (const float*)d_in[5];
    float* out = (float*)d_out;

    const int N = in_sizes[0] / D;   // 100000
    const int E = out_size;          // 800000

    detect_idx_kernel<<<1, 32>>>((const long long*)ei, N);

    cudaFuncSetAttribute(node_proj_kernel,
                         cudaFuncAttributeMaxDynamicSharedMemorySize, 196608);
    int grid = (N + 127) / 128;
    node_proj_kernel<<<grid, 512, 196608>>>(z, W1, b1, N);

    edge_kernel<<<2048, 256>>>(ei, W2, b2, out, E);
}

// round 3
// speedup vs baseline: 1.2944x; 1.2944x over previous
#include <cuda_runtime.h>
#include <cuda_bf16.h>
#include <stdint.h>

#define D 128
#define NMAX 100000
#define WPITCH 136            // bf16 elements per row (128 + 8 pad)
#define PITCHB (WPITCH * 2)   // 272 bytes

// ---------------------------------------------------------------------------
// Device scratch (static — no cudaMalloc allowed)
// ---------------------------------------------------------------------------
__device__ float g_A[(size_t)NMAX * D];   // z @ W1[:128]
__device__ float g_B[(size_t)NMAX * D];   // z @ W1[128:] + b1
// W1 pre-split to bf16 hi/lo, transposed to [n=256][k=128], pitch 136
__device__ __align__(16) __nv_bfloat16 g_Wh[256 * WPITCH];
__device__ __align__(16) __nv_bfloat16 g_Wl[256 * WPITCH];
__device__ int g_is64;

// ---------------------------------------------------------------------------
// PTX helpers (all plain sm_80-era features; safe on .target sm_103)
// ---------------------------------------------------------------------------
__device__ __forceinline__ uint32_t smem_u32(const void* p) {
    uint32_t a;
    asm("{ .reg .u64 t; cvta.to.shared.u64 t, %1; cvt.u32.u64 %0, t; }"
        : "=r"(a) : "l"(p));
    return a;
}

#define LDSM_X4(r0, r1, r2, r3, addr)                                        \
    asm volatile("ldmatrix.sync.aligned.m8n8.x4.shared.b16 {%0,%1,%2,%3},[%4];" \
                 : "=r"(r0), "=r"(r1), "=r"(r2), "=r"(r3) : "r"(addr))

#define LDSM_X2(r0, r1, addr)                                                \
    asm volatile("ldmatrix.sync.aligned.m8n8.x2.shared.b16 {%0,%1},[%2];"    \
                 : "=r"(r0), "=r"(r1) : "r"(addr))

#define MMA_BF16(d, a0, a1, a2, a3, b0, b1)                                  \
    asm volatile("mma.sync.aligned.m16n8k16.row.col.f32.bf16.bf16.f32 "      \
                 "{%0,%1,%2,%3},{%4,%5,%6,%7},{%8,%9},{%0,%1,%2,%3};"        \
                 : "+f"((d)[0]), "+f"((d)[1]), "+f"((d)[2]), "+f"((d)[3])    \
                 : "r"(a0), "r"(a1), "r"(a2), "r"(a3), "r"(b0), "r"(b1))

// ---------------------------------------------------------------------------
// Detect int64 vs int32 edge_index (JAX may demote to i32)
// ---------------------------------------------------------------------------
__global__ void detect_idx_kernel(const long long* __restrict__ ei, int N) {
    if (threadIdx.x == 0) {
        int ok = 1;
#pragma unroll
        for (int i = 0; i < 8; i++) {
            long long v = ei[i];
            if (v < 0 || v >= (long long)N) ok = 0;
        }
        g_is64 = ok;
    }
}

// ---------------------------------------------------------------------------
// Prep: W1 [256k x 128] fp32 -> bf16 hi/lo images, layout [n][k] pitch 136.
//   n < 128  -> column n of W1[:128]  (Wmat[n][k] = W1[k][n])
//   n >= 128 -> column n-128 of W1[128:]
// ---------------------------------------------------------------------------
__global__ void prep_w_kernel(const float* __restrict__ W1) {
    int i = blockIdx.x * blockDim.x + threadIdx.x;
    if (i >= 256 * 128) return;
    int n = i >> 7, k = i & 127;
    float x = (n < 128) ? W1[k * 128 + n] : W1[(128 + k) * 128 + (n - 128)];
    __nv_bfloat16 hi = __float2bfloat16_rn(x);
    __nv_bfloat16 lo = __float2bfloat16_rn(x - __bfloat162float(hi));
    g_Wh[n * WPITCH + k] = hi;
    g_Wl[n * WPITCH + k] = lo;
}

// ---------------------------------------------------------------------------
// Node projection via mma.sync bf16 (fp32 accum), 2-term split:
//   D = zh@Wh + zh@Wl + zl@Wh   (error ~2^-17, way under 1e-3)
// Persistent: 148 CTAs x 256 thr (8 warps). Per 128-row tile:
//   - z tile -> bf16 hi/lo in SMEM (pitch 136)
//   - warp w computes rows 0..127 x cols [w*32, w*32+32)
//   - TN ldmatrix (A and B both K-contiguous, non-trans)
// SMEM: zh 34816 | zl 34816 | Wh 69632 | Wl 69632 = 208896 B
// ---------------------------------------------------------------------------
__global__ void __launch_bounds__(256, 1)
node_mma_kernel(const float* __restrict__ z, const float* __restrict__ b1, int N)
{
    extern __shared__ char smem[];
    const uint32_t OF_ZH = 0;
    const uint32_t OF_ZL = 34816;
    const uint32_t OF_WH = 69632;
    const uint32_t OF_WL = 139264;

    const uint32_t sb = smem_u32(smem);
    const int tid = threadIdx.x;
    const int w = tid >> 5;
    const int lane = tid & 31;

    // Copy W images (139264 B) to SMEM once
    {
        const float4* sh = (const float4*)g_Wh;
        const float4* sl = (const float4*)g_Wl;
        float4* dh = (float4*)(smem + OF_WH);
        float4* dl = (float4*)(smem + OF_WL);
#pragma unroll
        for (int i = tid; i < 4352; i += 256) { dh[i] = sh[i]; dl[i] = sl[i]; }
    }

    // Per-lane ldmatrix offsets (TN layout, non-trans)
    const uint32_t a_off = (uint32_t)((lane & 15) * WPITCH + (lane >> 4) * 8) * 2;
    const uint32_t b_off = (uint32_t)((lane & 7) * WPITCH + ((lane >> 3) & 1) * 8) * 2;

    // b1 contribution for B-half warps (cols 128..255)
    float2 bb[4];
#pragma unroll
    for (int nt = 0; nt < 4; nt++) {
        if (w >= 4) {
            int c = (w - 4) * 32 + nt * 8 + (lane & 3) * 2;
            bb[nt] = make_float2(b1[c], b1[c + 1]);
        } else {
            bb[nt] = make_float2(0.f, 0.f);
        }
    }

    float* dstbase = (w < 4) ? g_A : g_B;
    const uint32_t wh_base = sb + ((w < 4) ? OF_WH : OF_WH) + (uint32_t)(w * 32) * PITCHB;
    const uint32_t wl_base = sb + OF_WL + (uint32_t)(w * 32) * PITCHB;
    const uint32_t whh = sb + OF_WH + (uint32_t)(w * 32) * PITCHB;
    (void)wh_base;

    const int ntiles = (N + 127) / 128;

    for (int t = blockIdx.x; t < ntiles; t += gridDim.x) {
        const int m0 = t * 128;

        __syncthreads();   // previous tile's ldmatrix reads complete

        // ---- z tile -> bf16 hi/lo SMEM ----
#pragma unroll
        for (int it = 0; it < 16; it++) {
            int i = tid + it * 256;          // [0, 4096)
            int m = i >> 5;                  // row 0..127
            int k4 = i & 31;                 // float4 along K
            float4 v = make_float4(0.f, 0.f, 0.f, 0.f);
            if (m0 + m < N)
                v = ((const float4*)z)[(size_t)(m0 + m) * 32 + k4];

            __nv_bfloat16 h0 = __float2bfloat16_rn(v.x);
            __nv_bfloat16 h1 = __float2bfloat16_rn(v.y);
            __nv_bfloat16 h2 = __float2bfloat16_rn(v.z);
            __nv_bfloat16 h3 = __float2bfloat16_rn(v.w);
            __nv_bfloat16 l0 = __float2bfloat16_rn(v.x - __bfloat162float(h0));
            __nv_bfloat16 l1 = __float2bfloat16_rn(v.y - __bfloat162float(h1));
            __nv_bfloat16 l2 = __float2bfloat16_rn(v.z - __bfloat162float(h2));
            __nv_bfloat16 l3 = __float2bfloat16_rn(v.w - __bfloat162float(h3));

            uint2 hv, lv;
            hv.x = (uint32_t)__bfloat16_as_ushort(h0) | ((uint32_t)__bfloat16_as_ushort(h1) << 16);
            hv.y = (uint32_t)__bfloat16_as_ushort(h2) | ((uint32_t)__bfloat16_as_ushort(h3) << 16);
            lv.x = (uint32_t)__bfloat16_as_ushort(l0) | ((uint32_t)__bfloat16_as_ushort(l1) << 16);
            lv.y = (uint32_t)__bfloat16_as_ushort(l2) | ((uint32_t)__bfloat16_as_ushort(l3) << 16);

            uint32_t so = (uint32_t)(m * WPITCH + k4 * 4) * 2;
            *(uint2*)(smem + OF_ZH + so) = hv;
            *(uint2*)(smem + OF_ZL + so) = lv;
        }
        __syncthreads();

        // ---- Compute: 3 split passes x 8 k-steps ----
        float acc[8][4][4];
#pragma unroll
        for (int mt = 0; mt < 8; mt++)
#pragma unroll
            for (int nt = 0; nt < 4; nt++)
#pragma unroll
                for (int q = 0; q < 4; q++) acc[mt][nt][q] = 0.f;

#pragma unroll
        for (int s = 0; s < 3; s++) {
            const uint32_t Abase = sb + ((s == 2) ? OF_ZL : OF_ZH) + a_off;
            const uint32_t Bbase = ((s == 1) ? wl_base : whh) + b_off;
#pragma unroll
            for (int ks = 0; ks < 8; ks++) {
                const uint32_t koff = (uint32_t)ks * 32;   // 16 bf16 = 32 B
                uint32_t br[8];
#pragma unroll
                for (int nt = 0; nt < 4; nt++)
                    LDSM_X2(br[2 * nt], br[2 * nt + 1],
                            Bbase + (uint32_t)(nt * 8) * PITCHB + koff);
#pragma unroll
                for (int mt = 0; mt < 8; mt++) {
                    uint32_t a0, a1, a2, a3;
                    LDSM_X4(a0, a1, a2, a3,
                            Abase + (uint32_t)(mt * 16) * PITCHB + koff);
#pragma unroll
                    for (int nt = 0; nt < 4; nt++)
                        MMA_BF16(acc[mt][nt], a0, a1, a2, a3,
                                 br[2 * nt], br[2 * nt + 1]);
                }
            }
        }

        // ---- Epilogue: accum regs -> g_A / g_B (+b1 on B half) ----
#pragma unroll
        for (int mt = 0; mt < 8; mt++) {
            int r0 = m0 + mt * 16 + (lane >> 2);
            int r1 = r0 + 8;
#pragma unroll
            for (int nt = 0; nt < 4; nt++) {
                int c = (w & 3) * 32 + nt * 8 + (lane & 3) * 2;
                if (r0 < N) {
                    float2 v = make_float2(acc[mt][nt][0] + bb[nt].x,
                                           acc[mt][nt][1] + bb[nt].y);
                    *(float2*)(dstbase + (size_t)r0 * 128 + c) = v;
                }
                if (r1 < N) {
                    float2 v = make_float2(acc[mt][nt][2] + bb[nt].x,
                                           acc[mt][nt][3] + bb[nt].y);
                    *(float2*)(dstbase + (size_t)r1 * 128 + c) = v;
                }
            }
        }
    }
}

// ---------------------------------------------------------------------------
// Edge pass: out[e] = relu(A[row] + B[col]) . W2 + b2   (one warp per edge)
// ---------------------------------------------------------------------------
__global__ void __launch_bounds__(256)
edge_kernel(const void* __restrict__ ei_raw,
            const float* __restrict__ W2,
            const float* __restrict__ b2,
            float* __restrict__ out, int E)
{
    const int lane = threadIdx.x & 31;
    const int warp = (blockIdx.x * blockDim.x + threadIdx.x) >> 5;
    const int nwarp = (gridDim.x * blockDim.x) >> 5;

    const float4 w2v = ((const float4*)W2)[lane];
    const float b2v = b2[0];
    const int is64 = g_is64;

    const long long* ei64 = (const long long*)ei_raw;
    const int*       ei32 = (const int*)ei_raw;

    for (int e = warp; e < E; e += nwarp) {
        int row, col;
        if (is64) {
            row = (int)ei64[e];
            col = (int)ei64[E + e];
        } else {
            row = ei32[e];
            col = ei32[E + e];
        }
        float4 av = ((const float4*)(g_A + (size_t)row * 128))[lane];
        float4 bv = ((const float4*)(g_B + (size_t)col * 128))[lane];

        float s = fmaxf(av.x + bv.x, 0.f) * w2v.x
                + fmaxf(av.y + bv.y, 0.f) * w2v.y
                + fmaxf(av.z + bv.z, 0.f) * w2v.z
                + fmaxf(av.w + bv.w, 0.f) * w2v.w;

#pragma unroll
        for (int o = 16; o; o >>= 1)
            s += __shfl_xor_sync(0xffffffffu, s, o);

        if (lane == 0) out[e] = s + b2v;
    }
}

// ---------------------------------------------------------------------------
// Launch
// ---------------------------------------------------------------------------
extern "C" void kernel_launch(void* const* d_in, const int* in_sizes, int n_in,
                              void* d_out, int out_size)
{
    const float* z  = (const float*)d_in[0];
    const void*  ei = d_in[1];
    const float* W1 = (const float*)d_in[2];
    const float* b1 = (const float*)d_in[3];
    const float* W2 = (const float*)d_in[4];
    const float* b2 = (const float*)d_in[5];
    float* out = (float*)d_out;

    const int N = in_sizes[0] / D;   // 100000
    const int E = out_size;          // 800000

    detect_idx_kernel<<<1, 32>>>((const long long*)ei, N);
    prep_w_kernel<<<128, 256>>>(W1);

    cudaFuncSetAttribute(node_mma_kernel,
                         cudaFuncAttributeMaxDynamicSharedMemorySize, 208896);
    node_mma_kernel<<<148, 256, 208896>>>(z, b1, N);

    edge_kernel<<<2048, 256>>>(ei, W2, b2, out, E);
}

// round 4
// speedup vs baseline: 1.9572x; 1.5121x over previous
#include <cuda_runtime.h>
#include <cuda_bf16.h>
#include <cuda_fp16.h>
#include <stdint.h>

#define D 128
#define NMAX 100000
#define NTILES_MAX 782
#define NPAD (NTILES_MAX * 128)      // 100096
#define WPITCH 136                   // bf16 elems per smem row (128 + 8 pad)
#define PITCHB 272                   // bytes

// ---------------------------------------------------------------------------
// Device scratch (static — no cudaMalloc allowed)
// ---------------------------------------------------------------------------
__device__ __align__(16) __nv_bfloat16 g_zh[(size_t)NPAD * 128];
__device__ __align__(16) __nv_bfloat16 g_zl[(size_t)NPAD * 128];
__device__ __align__(16) __half       g_A16[(size_t)NPAD * 128];  // z@W1[:128]
__device__ __align__(16) __half       g_B16[(size_t)NPAD * 128];  // z@W1[128:]+b1
__device__ __align__(16) __nv_bfloat16 g_Wh[256 * WPITCH];
__device__ __align__(16) __nv_bfloat16 g_Wl[256 * WPITCH];

// ---------------------------------------------------------------------------
// PTX helpers (sm_80-era only; safe on .target sm_103)
// ---------------------------------------------------------------------------
__device__ __forceinline__ uint32_t smem_u32(const void* p) {
    uint32_t a;
    asm("{ .reg .u64 t; cvta.to.shared.u64 t, %1; cvt.u32.u64 %0, t; }"
        : "=r"(a) : "l"(p));
    return a;
}

#define LDSM_X4(r0, r1, r2, r3, addr)                                           \
    asm volatile("ldmatrix.sync.aligned.m8n8.x4.shared.b16 {%0,%1,%2,%3},[%4];" \
                 : "=r"(r0), "=r"(r1), "=r"(r2), "=r"(r3) : "r"(addr))

#define LDSM_X2(r0, r1, addr)                                                \
    asm volatile("ldmatrix.sync.aligned.m8n8.x2.shared.b16 {%0,%1},[%2];"    \
                 : "=r"(r0), "=r"(r1) : "r"(addr))

#define MMA_BF16(d, a0, a1, a2, a3, b0, b1)                                  \
    asm volatile("mma.sync.aligned.m16n8k16.row.col.f32.bf16.bf16.f32 "      \
                 "{%0,%1,%2,%3},{%4,%5,%6,%7},{%8,%9},{%0,%1,%2,%3};"        \
                 : "+f"((d)[0]), "+f"((d)[1]), "+f"((d)[2]), "+f"((d)[3])    \
                 : "r"(a0), "r"(a1), "r"(a2), "r"(a3), "r"(b0), "r"(b1))

#define CP_ASYNC16(dst, src)                                                 \
    asm volatile("cp.async.cg.shared.global [%0], [%1], 16;"                 \
                 :: "r"(dst), "l"(src))
#define CP_COMMIT() asm volatile("cp.async.commit_group;" ::: "memory")
#define CP_WAIT1()  asm volatile("cp.async.wait_group 1;" ::: "memory")

// ---------------------------------------------------------------------------
// Prep: (a) W1 -> transposed bf16 hi/lo images [n=256][k=128] pitch 136
//       (b) z  -> bf16 hi/lo dense arrays [NPAD][128] (tail rows zeroed)
// ---------------------------------------------------------------------------
__global__ void prep_kernel(const float* __restrict__ z,
                            const float* __restrict__ W1, int N)
{
    int i = blockIdx.x * 256 + threadIdx.x;

    if (i < 256 * 128) {
        int n = i >> 7, k = i & 127;
        float x = (n < 128) ? W1[k * 128 + n] : W1[(128 + k) * 128 + (n - 128)];
        __nv_bfloat16 hi = __float2bfloat16_rn(x);
        __nv_bfloat16 lo = __float2bfloat16_rn(x - __bfloat162float(hi));
        g_Wh[n * WPITCH + k] = hi;
        g_Wl[n * WPITCH + k] = lo;
    }

    if (i < NPAD * 32) {
        int m = i >> 5, j = i & 31;
        float4 v = make_float4(0.f, 0.f, 0.f, 0.f);
        if (m < N) v = ((const float4*)z)[(size_t)m * 32 + j];

        __nv_bfloat16 h0 = __float2bfloat16_rn(v.x);
        __nv_bfloat16 h1 = __float2bfloat16_rn(v.y);
        __nv_bfloat16 h2 = __float2bfloat16_rn(v.z);
        __nv_bfloat16 h3 = __float2bfloat16_rn(v.w);
        __nv_bfloat16 l0 = __float2bfloat16_rn(v.x - __bfloat162float(h0));
        __nv_bfloat16 l1 = __float2bfloat16_rn(v.y - __bfloat162float(h1));
        __nv_bfloat16 l2 = __float2bfloat16_rn(v.z - __bfloat162float(h2));
        __nv_bfloat16 l3 = __float2bfloat16_rn(v.w - __bfloat162float(h3));

        uint2 hv, lv;
        hv.x = (uint32_t)__bfloat16_as_ushort(h0) | ((uint32_t)__bfloat16_as_ushort(h1) << 16);
        hv.y = (uint32_t)__bfloat16_as_ushort(h2) | ((uint32_t)__bfloat16_as_ushort(h3) << 16);
        lv.x = (uint32_t)__bfloat16_as_ushort(l0) | ((uint32_t)__bfloat16_as_ushort(l1) << 16);
        lv.y = (uint32_t)__bfloat16_as_ushort(l2) | ((uint32_t)__bfloat16_as_ushort(l3) << 16);

        ((uint2*)g_zh)[(size_t)m * 32 + j] = hv;
        ((uint2*)g_zl)[(size_t)m * 32 + j] = lv;
    }
}

// ---------------------------------------------------------------------------
// Node projection via mma.sync bf16, W fragments register-resident.
// 148 CTAs x 256 thr. CTA bid: hb = bid&1 selects output table (A or B);
// tiles t = bid>>1, stride 74. Warp w covers 128 rows x 16 cols.
// 3-pass split per tile: zh@Wh + zh@Wl + zl@Wh (fp32 accum).
// Smem: two 69632B buffers (zh 34816 + zl 34816 each), cp.async dbl-buffered.
// ---------------------------------------------------------------------------
__global__ void __launch_bounds__(256, 1)
node_mma_kernel(const float* __restrict__ b1, int N)
{
    extern __shared__ char smem[];
    const uint32_t sb = smem_u32(smem);
    const int tid = threadIdx.x;
    const int w = tid >> 5;
    const int lane = tid & 31;
    const int hb = blockIdx.x & 1;            // 0: A table, 1: B table
    const int tstart = blockIdx.x >> 1;       // 0..73
    const int ntiles = (N + 127) / 128;

    // ---- cp.async issue helper ----
    auto issue_tile = [&](int t, uint32_t bufbase) {
        const char* srch = (const char*)g_zh + (size_t)t * 32768;
        const char* srcl = (const char*)g_zl + (size_t)t * 32768;
#pragma unroll
        for (int q = 0; q < 8; q++) {
            int idx = tid + q * 256;          // 0..2047
            int m = idx >> 4, j = idx & 15;
            uint32_t dst = bufbase + (uint32_t)(m * 272 + j * 16);
            CP_ASYNC16(dst,         srch + m * 256 + j * 16);
            CP_ASYNC16(dst + 34816, srcl + m * 256 + j * 16);
        }
    };

    // Start loading first tile into buffer 1 (buffer 0 used as W scratch).
    if (tstart < ntiles) issue_tile(tstart, sb + 69632);
    CP_COMMIT();

    // ---- Load W fragments into registers (16 cols per warp, hi+lo) ----
    uint32_t whf[16][2], wlf[16][2];
    {
        const int n0 = hb * 128 + w * 16;
        const uint32_t scr = sb + (uint32_t)(w * 4352);
        const uint32_t boff = scr + (uint32_t)((lane & 7) * 272 + ((lane >> 3) & 1) * 16);

        // hi
#pragma unroll
        for (int q = 0; q < 8; q++) {
            int idx = lane + q * 32;          // 0..255
            int r = idx >> 4, j = idx & 15;
            *(float4*)(smem + (w * 4352 + r * 272 + j * 16)) =
                *(const float4*)((const char*)g_Wh + (size_t)(n0 + r) * PITCHB + j * 16);
        }
        __syncwarp();
#pragma unroll
        for (int ks = 0; ks < 8; ks++)
#pragma unroll
            for (int nt = 0; nt < 2; nt++)
                LDSM_X2(whf[ks * 2 + nt][0], whf[ks * 2 + nt][1],
                        boff + (uint32_t)(nt * 8 * 272 + ks * 32));
        __syncwarp();
        // lo
#pragma unroll
        for (int q = 0; q < 8; q++) {
            int idx = lane + q * 32;
            int r = idx >> 4, j = idx & 15;
            *(float4*)(smem + (w * 4352 + r * 272 + j * 16)) =
                *(const float4*)((const char*)g_Wl + (size_t)(n0 + r) * PITCHB + j * 16);
        }
        __syncwarp();
#pragma unroll
        for (int ks = 0; ks < 8; ks++)
#pragma unroll
            for (int nt = 0; nt < 2; nt++)
                LDSM_X2(wlf[ks * 2 + nt][0], wlf[ks * 2 + nt][1],
                        boff + (uint32_t)(nt * 8 * 272 + ks * 32));
    }
    __syncthreads();   // W scratch (buf 0) free before main loop cp.async into it

    // Bias (B table only)
    float2 bb0 = make_float2(0.f, 0.f), bb1 = bb0;
    if (hb) {
        int c = w * 16 + (lane & 3) * 2;
        bb0 = *(const float2*)(b1 + c);
        bb1 = *(const float2*)(b1 + c + 8);
    }
    __half* dsttab = hb ? g_B16 : g_A16;

    const uint32_t a_off = (uint32_t)((lane & 15) * WPITCH + (lane >> 4) * 8) * 2;

    int it = 1;
    for (int t = tstart; t < ntiles; t += 74) {
        int tn = t + 74;
        if (tn < ntiles) issue_tile(tn, sb + (uint32_t)((it ^ 1) * 69632));
        CP_COMMIT();
        CP_WAIT1();
        __syncthreads();

        const uint32_t Ah = sb + (uint32_t)(it * 69632) + a_off;
        const uint32_t Al = Ah + 34816;

        float acc[8][2][4];
#pragma unroll
        for (int mt = 0; mt < 8; mt++)
#pragma unroll
            for (int nt = 0; nt < 2; nt++)
#pragma unroll
                for (int q = 0; q < 4; q++) acc[mt][nt][q] = 0.f;

#pragma unroll
        for (int ks = 0; ks < 8; ks++) {
            const uint32_t ko = (uint32_t)ks * 32;
#pragma unroll
            for (int mt = 0; mt < 8; mt++) {
                uint32_t a0, a1, a2, a3;
                LDSM_X4(a0, a1, a2, a3, Ah + (uint32_t)(mt * 16 * 272) + ko);
                MMA_BF16(acc[mt][0], a0, a1, a2, a3, whf[ks * 2 + 0][0], whf[ks * 2 + 0][1]);
                MMA_BF16(acc[mt][1], a0, a1, a2, a3, whf[ks * 2 + 1][0], whf[ks * 2 + 1][1]);
                MMA_BF16(acc[mt][0], a0, a1, a2, a3, wlf[ks * 2 + 0][0], wlf[ks * 2 + 0][1]);
                MMA_BF16(acc[mt][1], a0, a1, a2, a3, wlf[ks * 2 + 1][0], wlf[ks * 2 + 1][1]);
                uint32_t c0, c1, c2, c3;
                LDSM_X4(c0, c1, c2, c3, Al + (uint32_t)(mt * 16 * 272) + ko);
                MMA_BF16(acc[mt][0], c0, c1, c2, c3, whf[ks * 2 + 0][0], whf[ks * 2 + 0][1]);
                MMA_BF16(acc[mt][1], c0, c1, c2, c3, whf[ks * 2 + 1][0], whf[ks * 2 + 1][1]);
            }
        }

        // Epilogue: fp16 stores (+bias on B table)
        const int m0 = t * 128;
#pragma unroll
        for (int mt = 0; mt < 8; mt++) {
            int r0 = m0 + mt * 16 + (lane >> 2);
#pragma unroll
            for (int nt = 0; nt < 2; nt++) {
                float2 b = nt ? bb1 : bb0;
                int c = w * 16 + nt * 8 + (lane & 3) * 2;
                if (r0 < N)
                    *(half2*)(dsttab + (size_t)r0 * 128 + c) =
                        __floats2half2_rn(acc[mt][nt][0] + b.x, acc[mt][nt][1] + b.y);
                if (r0 + 8 < N)
                    *(half2*)(dsttab + (size_t)(r0 + 8) * 128 + c) =
                        __floats2half2_rn(acc[mt][nt][2] + b.x, acc[mt][nt][3] + b.y);
            }
        }
        __syncthreads();   // all reads of buf[it] done before it's refilled
        it ^= 1;
    }
}

// ---------------------------------------------------------------------------
// Edge pass: out[e] = relu(A16[row] + B16[col]) . W2 + b2
// 16 lanes per edge (2 edges per warp); inline int64/int32 detection.
// ---------------------------------------------------------------------------
__global__ void __launch_bounds__(256)
edge_kernel(const void* __restrict__ ei_raw,
            const float* __restrict__ W2,
            const float* __restrict__ b2,
            float* __restrict__ out, int E, int N)
{
    const long long* ei64 = (const long long*)ei_raw;
    const int*       ei32 = (const int*)ei_raw;

    int is64 = 1;
#pragma unroll
    for (int i = 0; i < 8; i++) {
        long long v = __ldg(&ei64[i]);
        if (v < 0 || v >= (long long)N) is64 = 0;
    }

    const int lane = threadIdx.x & 31;
    const int sub = lane >> 4;     // which edge of the pair
    const int sl  = lane & 15;     // lane within edge (8 dims each)

    const float4 w2a = ((const float4*)W2)[sl * 2];
    const float4 w2b = ((const float4*)W2)[sl * 2 + 1];
    const float b2v = __ldg(b2);

    const int warp = (blockIdx.x * 256 + threadIdx.x) >> 5;
    const int nwarp = (gridDim.x * 256) >> 5;
    const int npairs = (E + 1) >> 1;

    for (int p = warp; p < npairs; p += nwarp) {
        int e = p * 2 + sub;
        if (e >= E) continue;
        int row, col;
        if (is64) {
            row = (int)ei64[e];
            col = (int)ei64[E + e];
        } else {
            row = ei32[e];
            col = ei32[E + e];
        }
        uint4 a4 = *(const uint4*)(g_A16 + (size_t)row * 128 + sl * 8);
        uint4 b4 = *(const uint4*)(g_B16 + (size_t)col * 128 + sl * 8);

        float2 a0 = __half22float2(*(const half2*)&a4.x);
        float2 a1 = __half22float2(*(const half2*)&a4.y);
        float2 a2 = __half22float2(*(const half2*)&a4.z);
        float2 a3 = __half22float2(*(const half2*)&a4.w);
        float2 c0 = __half22float2(*(const half2*)&b4.x);
        float2 c1 = __half22float2(*(const half2*)&b4.y);
        float2 c2 = __half22float2(*(const half2*)&b4.z);
        float2 c3 = __half22float2(*(const half2*)&b4.w);

        float s = fmaxf(a0.x + c0.x, 0.f) * w2a.x
                + fmaxf(a0.y + c0.y, 0.f) * w2a.y
                + fmaxf(a1.x + c1.x, 0.f) * w2a.z
                + fmaxf(a1.y + c1.y, 0.f) * w2a.w
                + fmaxf(a2.x + c2.x, 0.f) * w2b.x
                + fmaxf(a2.y + c2.y, 0.f) * w2b.y
                + fmaxf(a3.x + c3.x, 0.f) * w2b.z
                + fmaxf(a3.y + c3.y, 0.f) * w2b.w;

#pragma unroll
        for (int o = 8; o; o >>= 1)
            s += __shfl_xor_sync(0xffffffffu, s, o);

        if (sl == 0) out[e] = s + b2v;
    }
}

// ---------------------------------------------------------------------------
// Launch
// ---------------------------------------------------------------------------
extern "C" void kernel_launch(void* const* d_in, const int* in_sizes, int n_in,
                              void* d_out, int out_size)
{
    const float* z  = (const float*)d_in[0];
    const void*  ei = d_in[1];
    const float* W1 = (const float*)d_in[2];
    const float* b1 = (const float*)d_in[3];
    const float* W2 = (const float*)d_in[4];
    const float* b2 = (const float*)d_in[5];
    float* out = (float*)d_out;

    const int N = in_sizes[0] / D;   // 100000
    const int E = out_size;          // 800000

    prep_kernel<<<(NPAD * 32 + 255) / 256, 256>>>(z, W1, N);

    cudaFuncSetAttribute(node_mma_kernel,
                         cudaFuncAttributeMaxDynamicSharedMemorySize, 139264);
    node_mma_kernel<<<148, 256, 139264>>>(b1, N);

    edge_kernel<<<2048, 256>>>(ei, W2, b2, out, E, N);
}

// round 5
// speedup vs baseline: 2.2446x; 1.1468x over previous
#include <cuda_runtime.h>
#include <cuda_bf16.h>
#include <cuda_fp16.h>
#include <stdint.h>

#define D 128
#define NMAX 100000
#define WPITCH 136                   // bf16 elems per smem row (128 + 8 pad)
#define PITCHB 272                   // bytes

// ---------------------------------------------------------------------------
// Device scratch (static — no cudaMalloc allowed)
// ---------------------------------------------------------------------------
__device__ __align__(16) __half g_A16[(size_t)(NMAX + 128) * 128];  // z@W1[:128]
__device__ __align__(16) __half g_B16[(size_t)(NMAX + 128) * 128];  // z@W1[128:]+b1

// ---------------------------------------------------------------------------
// PTX helpers (sm_80-era only; safe on .target sm_103)
// ---------------------------------------------------------------------------
__device__ __forceinline__ uint32_t smem_u32(const void* p) {
    uint32_t a;
    asm("{ .reg .u64 t; cvta.to.shared.u64 t, %1; cvt.u32.u64 %0, t; }"
        : "=r"(a) : "l"(p));
    return a;
}

#define LDSM_X4(r0, r1, r2, r3, addr)                                           \
    asm volatile("ldmatrix.sync.aligned.m8n8.x4.shared.b16 {%0,%1,%2,%3},[%4];" \
                 : "=r"(r0), "=r"(r1), "=r"(r2), "=r"(r3) : "r"(addr))

#define LDSM_X2(r0, r1, addr)                                                \
    asm volatile("ldmatrix.sync.aligned.m8n8.x2.shared.b16 {%0,%1},[%2];"    \
                 : "=r"(r0), "=r"(r1) : "r"(addr))

#define MMA_BF16(d, a0, a1, a2, a3, b0, b1)                                  \
    asm volatile("mma.sync.aligned.m16n8k16.row.col.f32.bf16.bf16.f32 "      \
                 "{%0,%1,%2,%3},{%4,%5,%6,%7},{%8,%9},{%0,%1,%2,%3};"        \
                 : "+f"((d)[0]), "+f"((d)[1]), "+f"((d)[2]), "+f"((d)[3])    \
                 : "r"(a0), "r"(a1), "r"(a2), "r"(a3), "r"(b0), "r"(b1))

#define CP_ASYNC16(dst, src)                                                 \
    asm volatile("cp.async.cg.shared.global [%0], [%1], 16;"                 \
                 :: "r"(dst), "l"(src))
#define CP_COMMIT() asm volatile("cp.async.commit_group;" ::: "memory")
#define CP_WAIT1()  asm volatile("cp.async.wait_group 1;" ::: "memory")

// packed f32x2 -> bf16x2 convert (1 instruction)
__device__ __forceinline__ uint32_t cvt_bf16x2(float hi, float lo) {
    uint32_t r;
    asm("cvt.rn.bf16x2.f32 %0, %1, %2;" : "=r"(r) : "f"(hi), "f"(lo));
    return r;
}

// split two f32 into bf16x2 hi + bf16x2 lo (residual)
__device__ __forceinline__ void split2(float x, float y,
                                       uint32_t& h, uint32_t& l) {
    h = cvt_bf16x2(y, x);                 // [y_bf | x_bf]
    float fx = __uint_as_float(h << 16);          // x_bf as f32
    float fy = __uint_as_float(h & 0xffff0000u);  // y_bf as f32
    l = cvt_bf16x2(y - fy, x - fx);
}

// ---------------------------------------------------------------------------
// Node projection via mma.sync bf16 (fp32 accum), 3-term split:
//   D = zh@Wh + zh@Wl + zl@Wh
// 148 CTAs x 256 thr. hb = bid&1: output table (A or B); tiles stride 74.
// Per tile: cp.async raw fp32 z (dbl-buffered) -> in-kernel bf16 hi/lo split
// -> ldmatrix -> MMA with register-resident W fragments -> fp16 stores.
// SMEM: raw0 64K | raw1 64K | conv hi 34816 + lo 34816  = 200704 B
// ---------------------------------------------------------------------------
__global__ void __launch_bounds__(256, 1)
node_mma_kernel(const float* __restrict__ z, const float* __restrict__ W1,
                const float* __restrict__ b1, int N)
{
    extern __shared__ char smem[];
    const uint32_t OF_RAW0 = 0;
    const uint32_t OF_RAW1 = 65536;
    const uint32_t OF_CH   = 131072;            // conv hi
    const uint32_t OF_CL   = 131072 + 34816;    // conv lo

    const uint32_t sb = smem_u32(smem);
    const int tid = threadIdx.x;
    const int w = tid >> 5;
    const int lane = tid & 31;
    const int hb = blockIdx.x & 1;            // 0: A table, 1: B table
    const int tstart = blockIdx.x >> 1;       // 0..73
    const int ntiles = (N + 127) / 128;

    // ---- cp.async raw fp32 tile (zero-fill OOB rows) ----
    auto issue_tile = [&](int t, uint32_t bufoff) {
        const char* src = (const char*)z + (size_t)t * 128 * 512;
        const int rows_valid = N - t * 128;   // may exceed 128
#pragma unroll
        for (int q = 0; q < 16; q++) {
            int idx = tid + q * 256;          // 0..4095
            int m = idx >> 5, j = idx & 31;
            uint32_t off = bufoff + (uint32_t)(m * 512 + j * 16);
            if (m < rows_valid)
                CP_ASYNC16(sb + off, src + m * 512 + j * 16);
            else
                *(float4*)(smem + off) = make_float4(0.f, 0.f, 0.f, 0.f);
        }
    };

    if (tstart < ntiles) issue_tile(tstart, OF_RAW0);
    CP_COMMIT();

    // ---- W1 -> bf16 hi/lo fragments in registers (16 cols per warp) ----
    uint32_t whf[16][2], wlf[16][2];
    {
        const int n0 = w * 16;
        const uint32_t stg = (uint32_t)(OF_CH + w * 4352);
        const uint32_t boff = sb + stg
            + (uint32_t)((lane & 7) * 272 + ((lane >> 3) & 1) * 16);

        // stage hi and lo into per-warp scratch, one after the other
#pragma unroll
        for (int q = 0; q < 64; q++) {        // 2048 elems / 32 lanes
            int idx = lane + q * 32;
            int r = idx & 15, k = idx >> 4;   // r: col-in-slice, k: 0..127
            float x = W1[(size_t)(hb * 128 + k) * 128 + n0 + r];
            __nv_bfloat16 hi = __float2bfloat16_rn(x);
            *(__nv_bfloat16*)(smem + stg + r * 272 + k * 2) = hi;
        }
        __syncwarp();
#pragma unroll
        for (int ks = 0; ks < 8; ks++)
#pragma unroll
            for (int nt = 0; nt < 2; nt++)
                LDSM_X2(whf[ks * 2 + nt][0], whf[ks * 2 + nt][1],
                        boff + (uint32_t)(nt * 8 * 272 + ks * 32));
        __syncwarp();
#pragma unroll
        for (int q = 0; q < 64; q++) {
            int idx = lane + q * 32;
            int r = idx & 15, k = idx >> 4;
            float x = W1[(size_t)(hb * 128 + k) * 128 + n0 + r];
            __nv_bfloat16 hi = __float2bfloat16_rn(x);
            __nv_bfloat16 lo = __float2bfloat16_rn(x - __bfloat162float(hi));
            *(__nv_bfloat16*)(smem + stg + r * 272 + k * 2) = lo;
        }
        __syncwarp();
#pragma unroll
        for (int ks = 0; ks < 8; ks++)
#pragma unroll
            for (int nt = 0; nt < 2; nt++)
                LDSM_X2(wlf[ks * 2 + nt][0], wlf[ks * 2 + nt][1],
                        boff + (uint32_t)(nt * 8 * 272 + ks * 32));
    }
    __syncthreads();   // conv scratch free before main loop

    // Bias (B table only)
    float2 bb0 = make_float2(0.f, 0.f), bb1 = bb0;
    if (hb) {
        int c = w * 16 + (lane & 3) * 2;
        bb0 = *(const float2*)(b1 + c);
        bb1 = *(const float2*)(b1 + c + 8);
    }
    __half* dsttab = hb ? g_B16 : g_A16;

    const uint32_t a_off = (uint32_t)((lane & 15) * WPITCH + (lane >> 4) * 8) * 2;
    const uint32_t Ah = sb + OF_CH + a_off;
    const uint32_t Al = sb + OF_CL + a_off;

    int it = 0;
    for (int t = tstart; t < ntiles; t += 74) {
        int tn = t + 74;
        if (tn < ntiles) issue_tile(tn, it ? OF_RAW0 : OF_RAW1);
        CP_COMMIT();
        CP_WAIT1();
        __syncthreads();   // raw[it] ready; also: prior MMA reads of conv done

        // ---- convert raw fp32 -> bf16 hi/lo (pitched for ldmatrix) ----
        {
            const uint32_t rawoff = it ? OF_RAW1 : OF_RAW0;
#pragma unroll
            for (int q = 0; q < 16; q++) {
                int idx = tid + q * 256;       // 0..4095
                int m = idx >> 5, j = idx & 31;
                float4 v = *(const float4*)(smem + rawoff + m * 512 + j * 16);
                uint32_t h0, l0, h1, l1;
                split2(v.x, v.y, h0, l0);
                split2(v.z, v.w, h1, l1);
                uint32_t co = (uint32_t)(m * 272 + j * 8);
                *(uint2*)(smem + OF_CH + co) = make_uint2(h0, h1);
                *(uint2*)(smem + OF_CL + co) = make_uint2(l0, l1);
            }
        }
        __syncthreads();

        // ---- MMA: 8 k-steps x 8 m-tiles x 6 MMAs ----
        float acc[8][2][4];
#pragma unroll
        for (int mt = 0; mt < 8; mt++)
#pragma unroll
            for (int nt = 0; nt < 2; nt++)
#pragma unroll
                for (int q = 0; q < 4; q++) acc[mt][nt][q] = 0.f;

#pragma unroll
        for (int ks = 0; ks < 8; ks++) {
            const uint32_t ko = (uint32_t)ks * 32;
#pragma unroll
            for (int mt = 0; mt < 8; mt++) {
                uint32_t a0, a1, a2, a3;
                LDSM_X4(a0, a1, a2, a3, Ah + (uint32_t)(mt * 16 * 272) + ko);
                MMA_BF16(acc[mt][0], a0, a1, a2, a3, whf[ks * 2 + 0][0], whf[ks * 2 + 0][1]);
                MMA_BF16(acc[mt][1], a0, a1, a2, a3, whf[ks * 2 + 1][0], whf[ks * 2 + 1][1]);
                MMA_BF16(acc[mt][0], a0, a1, a2, a3, wlf[ks * 2 + 0][0], wlf[ks * 2 + 0][1]);
                MMA_BF16(acc[mt][1], a0, a1, a2, a3, wlf[ks * 2 + 1][0], wlf[ks * 2 + 1][1]);
                uint32_t c0, c1, c2, c3;
                LDSM_X4(c0, c1, c2, c3, Al + (uint32_t)(mt * 16 * 272) + ko);
                MMA_BF16(acc[mt][0], c0, c1, c2, c3, whf[ks * 2 + 0][0], whf[ks * 2 + 0][1]);
                MMA_BF16(acc[mt][1], c0, c1, c2, c3, whf[ks * 2 + 1][0], whf[ks * 2 + 1][1]);
            }
        }

        // ---- Epilogue: fp16 stores (+bias on B table) ----
        const int m0 = t * 128;
#pragma unroll
        for (int mt = 0; mt < 8; mt++) {
            int r0 = m0 + mt * 16 + (lane >> 2);
#pragma unroll
            for (int nt = 0; nt < 2; nt++) {
                float2 b = nt ? bb1 : bb0;
                int c = w * 16 + nt * 8 + (lane & 3) * 2;
                if (r0 < N)
                    *(half2*)(dsttab + (size_t)r0 * 128 + c) =
                        __floats2half2_rn(acc[mt][nt][0] + b.x, acc[mt][nt][1] + b.y);
                if (r0 + 8 < N)
                    *(half2*)(dsttab + (size_t)(r0 + 8) * 128 + c) =
                        __floats2half2_rn(acc[mt][nt][2] + b.x, acc[mt][nt][3] + b.y);
            }
        }
        it ^= 1;
    }
}

// ---------------------------------------------------------------------------
// Edge pass: out[e] = relu(A16[row] + B16[col]) . W2 + b2
// 16 lanes per edge (2 edges/warp), 2-pair unroll for MLP.
// ---------------------------------------------------------------------------
__device__ __forceinline__ float edge_dot(uint4 a4, uint4 b4,
                                          float4 w2a, float4 w2b) {
    float2 a0 = __half22float2(*(const half2*)&a4.x);
    float2 a1 = __half22float2(*(const half2*)&a4.y);
    float2 a2 = __half22float2(*(const half2*)&a4.z);
    float2 a3 = __half22float2(*(const half2*)&a4.w);
    float2 c0 = __half22float2(*(const half2*)&b4.x);
    float2 c1 = __half22float2(*(const half2*)&b4.y);
    float2 c2 = __half22float2(*(const half2*)&b4.z);
    float2 c3 = __half22float2(*(const half2*)&b4.w);
    return fmaxf(a0.x + c0.x, 0.f) * w2a.x
         + fmaxf(a0.y + c0.y, 0.f) * w2a.y
         + fmaxf(a1.x + c1.x, 0.f) * w2a.z
         + fmaxf(a1.y + c1.y, 0.f) * w2a.w
         + fmaxf(a2.x + c2.x, 0.f) * w2b.x
         + fmaxf(a2.y + c2.y, 0.f) * w2b.y
         + fmaxf(a3.x + c3.x, 0.f) * w2b.z
         + fmaxf(a3.y + c3.y, 0.f) * w2b.w;
}

__global__ void __launch_bounds__(256)
edge_kernel(const void* __restrict__ ei_raw,
            const float* __restrict__ W2,
            const float* __restrict__ b2,
            float* __restrict__ out, int E, int N)
{
    const long long* ei64 = (const long long*)ei_raw;
    const int*       ei32 = (const int*)ei_raw;

    int is64 = 1;
#pragma unroll
    for (int i = 0; i < 8; i++) {
        long long v = __ldg(&ei64[i]);
        if (v < 0 || v >= (long long)N) is64 = 0;
    }

    const int lane = threadIdx.x & 31;
    const int sub = lane >> 4;     // which edge of the pair
    const int sl  = lane & 15;     // lane within edge

    const float4 w2a = ((const float4*)W2)[sl * 2];
    const float4 w2b = ((const float4*)W2)[sl * 2 + 1];
    const float b2v = __ldg(b2);

    const int warp = (blockIdx.x * 256 + threadIdx.x) >> 5;
    const int nwarp = (gridDim.x * 256) >> 5;
    const int npairs = (E + 1) >> 1;

    for (int p = warp; p < npairs; p += 2 * nwarp) {
        const int pB = p + nwarp;
        const int e1 = p * 2 + sub;
        const int e2 = pB * 2 + sub;
        const bool hasB = (pB < npairs) && (e2 < E);

        int r1, c1, r2 = 0, c2 = 0;
        if (is64) {
            r1 = (int)ei64[e1];  c1 = (int)ei64[E + e1];
            if (hasB) { r2 = (int)ei64[e2];  c2 = (int)ei64[E + e2]; }
        } else {
            r1 = ei32[e1];  c1 = ei32[E + e1];
            if (hasB) { r2 = ei32[e2];  c2 = ei32[E + e2]; }
        }

        uint4 a1 = *(const uint4*)(g_A16 + (size_t)r1 * 128 + sl * 8);
        uint4 b1 = *(const uint4*)(g_B16 + (size_t)c1 * 128 + sl * 8);
        uint4 a2 = make_uint4(0, 0, 0, 0), b2q = a2;
        if (hasB) {
            a2 = *(const uint4*)(g_A16 + (size_t)r2 * 128 + sl * 8);
            b2q = *(const uint4*)(g_B16 + (size_t)c2 * 128 + sl * 8);
        }

        float s1 = edge_dot(a1, b1, w2a, w2b);
        float s2 = edge_dot(a2, b2q, w2a, w2b);
#pragma unroll
        for (int o = 8; o; o >>= 1) {
            s1 += __shfl_xor_sync(0xffffffffu, s1, o);
            s2 += __shfl_xor_sync(0xffffffffu, s2, o);
        }

        if (sl == 0) {
            if (e1 < E) out[e1] = s1 + b2v;
            if (hasB)   out[e2] = s2 + b2v;
        }
    }
}

// ---------------------------------------------------------------------------
// Launch
// ---------------------------------------------------------------------------
extern "C" void kernel_launch(void* const* d_in, const int* in_sizes, int n_in,
                              void* d_out, int out_size)
{
    const float* z  = (const float*)d_in[0];
    const void*  ei = d_in[1];
    const float* W1 = (const float*)d_in[2];
    const float* b1 = (const float*)d_in[3];
    const float* W2 = (const float*)d_in[4];
    const float* b2 = (const float*)d_in[5];
    float* out = (float*)d_out;

    const int N = in_sizes[0] / D;   // 100000
    const int E = out_size;          // 800000

    cudaFuncSetAttribute(node_mma_kernel,
                         cudaFuncAttributeMaxDynamicSharedMemorySize, 200704);
    node_mma_kernel<<<148, 256, 200704>>>(z, W1, b1, N);

    edge_kernel<<<1184, 256>>>(ei, W2, b2, out, E, N);
}

// round 6
// speedup vs baseline: 2.4050x; 1.0715x over previous
#include <cuda_runtime.h>
#include <cuda_bf16.h>
#include <cuda_fp16.h>
#include <stdint.h>

#define D 128
#define NMAX 100000
#define WPITCH 136                   // bf16 elems per smem row (128 + 8 pad)
#define PITCHB 272                   // bytes

// ---------------------------------------------------------------------------
// Device scratch (static — no cudaMalloc allowed)
// ---------------------------------------------------------------------------
__device__ __align__(16) __half g_A16[(size_t)(NMAX + 128) * 128];  // z@W1[:128]
__device__ __align__(16) __half g_B16[(size_t)(NMAX + 128) * 128];  // z@W1[128:]+b1

// ---------------------------------------------------------------------------
// PTX helpers (sm_80-era only; safe on .target sm_103)
// ---------------------------------------------------------------------------
__device__ __forceinline__ uint32_t smem_u32(const void* p) {
    uint32_t a;
    asm("{ .reg .u64 t; cvta.to.shared.u64 t, %1; cvt.u32.u64 %0, t; }"
        : "=r"(a) : "l"(p));
    return a;
}

#define LDSM_X4(r0, r1, r2, r3, addr)                                           \
    asm volatile("ldmatrix.sync.aligned.m8n8.x4.shared.b16 {%0,%1,%2,%3},[%4];" \
                 : "=r"(r0), "=r"(r1), "=r"(r2), "=r"(r3) : "r"(addr))

#define LDSM_X2(r0, r1, addr)                                                \
    asm volatile("ldmatrix.sync.aligned.m8n8.x2.shared.b16 {%0,%1},[%2];"    \
                 : "=r"(r0), "=r"(r1) : "r"(addr))

#define MMA_BF16(d, a0, a1, a2, a3, b0, b1)                                  \
    asm volatile("mma.sync.aligned.m16n8k16.row.col.f32.bf16.bf16.f32 "      \
                 "{%0,%1,%2,%3},{%4,%5,%6,%7},{%8,%9},{%0,%1,%2,%3};"        \
                 : "+f"((d)[0]), "+f"((d)[1]), "+f"((d)[2]), "+f"((d)[3])    \
                 : "r"(a0), "r"(a1), "r"(a2), "r"(a3), "r"(b0), "r"(b1))

#define CP_ASYNC16(dst, src)                                                 \
    asm volatile("cp.async.cg.shared.global [%0], [%1], 16;"                 \
                 :: "r"(dst), "l"(src))
#define CP_COMMIT() asm volatile("cp.async.commit_group;" ::: "memory")
#define CP_WAIT1()  asm volatile("cp.async.wait_group 1;" ::: "memory")

// packed f32x2 -> bf16x2 convert (1 instruction)
__device__ __forceinline__ uint32_t cvt_bf16x2(float hi, float lo) {
    uint32_t r;
    asm("cvt.rn.bf16x2.f32 %0, %1, %2;" : "=r"(r) : "f"(hi), "f"(lo));
    return r;
}

// split two f32 into bf16x2 hi + bf16x2 lo (residual)
__device__ __forceinline__ void split2(float x, float y,
                                       uint32_t& h, uint32_t& l) {
    h = cvt_bf16x2(y, x);                 // [y_bf | x_bf]
    float fx = __uint_as_float(h << 16);          // x_bf as f32
    float fy = __uint_as_float(h & 0xffff0000u);  // y_bf as f32
    l = cvt_bf16x2(y - fy, x - fx);
}

// ---------------------------------------------------------------------------
// Node projection via mma.sync bf16 (fp32 accum), 3-term split:
//   D = zh@Wh + zh@Wl + zl@Wh
// 296 CTAs x 256 thr, 2 CTAs/SM (98KB smem each). hb = bid&1 selects table;
// tiles of 64 rows, stride 148. cp.async fp32 z (dbl-buffered) ->
// in-kernel bf16 split -> ldmatrix -> MMA (W fragments in registers).
// SMEM: raw0 32K | raw1 32K | conv hi 17408 | conv lo 17408 = 100352 B
// ---------------------------------------------------------------------------
__global__ void __launch_bounds__(256, 2)
node_mma_kernel(const float* __restrict__ z, const float* __restrict__ W1,
                const float* __restrict__ b1, int N)
{
    extern __shared__ char smem[];
    const uint32_t OF_RAW0 = 0;
    const uint32_t OF_RAW1 = 32768;
    const uint32_t OF_CH   = 65536;            // conv hi (64 rows x 272B)
    const uint32_t OF_CL   = 65536 + 17408;    // conv lo

    const uint32_t sb = smem_u32(smem);
    const int tid = threadIdx.x;
    const int w = tid >> 5;
    const int lane = tid & 31;
    const int hb = blockIdx.x & 1;            // 0: A table, 1: B table
    const int tstart = blockIdx.x >> 1;       // 0..147
    const int ntiles = (N + 63) / 64;

    // ---- cp.async raw fp32 tile: 64 rows x 512 B (zero-fill OOB rows) ----
    auto issue_tile = [&](int t, uint32_t bufoff) {
        const char* src = (const char*)z + (size_t)t * 64 * 512;
        const int rows_valid = N - t * 64;
#pragma unroll
        for (int q = 0; q < 8; q++) {
            int idx = tid + q * 256;          // 0..2047
            int m = idx >> 5, j = idx & 31;
            uint32_t off = bufoff + (uint32_t)(m * 512 + j * 16);
            if (m < rows_valid)
                CP_ASYNC16(sb + off, src + m * 512 + j * 16);
            else
                *(float4*)(smem + off) = make_float4(0.f, 0.f, 0.f, 0.f);
        }
    };

    if (tstart < ntiles) issue_tile(tstart, OF_RAW0);
    CP_COMMIT();

    // ---- W1 -> bf16 hi/lo fragments in registers (16 cols per warp) ----
    // Scratch: conv region (34816 B total = 8 warps x 4352 B)
    uint32_t whf[16][2], wlf[16][2];
    {
        const int n0 = w * 16;
        const uint32_t stg = (uint32_t)(OF_CH + w * 4352);
        const uint32_t boff = sb + stg
            + (uint32_t)((lane & 7) * 272 + ((lane >> 3) & 1) * 16);

#pragma unroll
        for (int q = 0; q < 64; q++) {        // 2048 elems / 32 lanes
            int idx = lane + q * 32;
            int r = idx & 15, k = idx >> 4;
            float x = W1[(size_t)(hb * 128 + k) * 128 + n0 + r];
            __nv_bfloat16 hi = __float2bfloat16_rn(x);
            *(__nv_bfloat16*)(smem + stg + r * 272 + k * 2) = hi;
        }
        __syncwarp();
#pragma unroll
        for (int ks = 0; ks < 8; ks++)
#pragma unroll
            for (int nt = 0; nt < 2; nt++)
                LDSM_X2(whf[ks * 2 + nt][0], whf[ks * 2 + nt][1],
                        boff + (uint32_t)(nt * 8 * 272 + ks * 32));
        __syncwarp();
#pragma unroll
        for (int q = 0; q < 64; q++) {
            int idx = lane + q * 32;
            int r = idx & 15, k = idx >> 4;
            float x = W1[(size_t)(hb * 128 + k) * 128 + n0 + r];
            __nv_bfloat16 hi = __float2bfloat16_rn(x);
            __nv_bfloat16 lo = __float2bfloat16_rn(x - __bfloat162float(hi));
            *(__nv_bfloat16*)(smem + stg + r * 272 + k * 2) = lo;
        }
        __syncwarp();
#pragma unroll
        for (int ks = 0; ks < 8; ks++)
#pragma unroll
            for (int nt = 0; nt < 2; nt++)
                LDSM_X2(wlf[ks * 2 + nt][0], wlf[ks * 2 + nt][1],
                        boff + (uint32_t)(nt * 8 * 272 + ks * 32));
    }
    __syncthreads();   // conv scratch free before main loop

    // Bias (B table only)
    float2 bb0 = make_float2(0.f, 0.f), bb1 = bb0;
    if (hb) {
        int c = w * 16 + (lane & 3) * 2;
        bb0 = *(const float2*)(b1 + c);
        bb1 = *(const float2*)(b1 + c + 8);
    }
    __half* dsttab = hb ? g_B16 : g_A16;

    const uint32_t a_off = (uint32_t)((lane & 15) * WPITCH + (lane >> 4) * 8) * 2;
    const uint32_t Ah = sb + OF_CH + a_off;
    const uint32_t Al = sb + OF_CL + a_off;

    int it = 0;
    for (int t = tstart; t < ntiles; t += 148) {
        int tn = t + 148;
        if (tn < ntiles) issue_tile(tn, it ? OF_RAW0 : OF_RAW1);
        CP_COMMIT();
        CP_WAIT1();
        __syncthreads();   // raw[it] ready; prior MMA reads of conv done

        // ---- convert raw fp32 -> bf16 hi/lo (pitched for ldmatrix) ----
        {
            const uint32_t rawoff = it ? OF_RAW1 : OF_RAW0;
#pragma unroll
            for (int q = 0; q < 8; q++) {
                int idx = tid + q * 256;       // 0..2047
                int m = idx >> 5, j = idx & 31;
                float4 v = *(const float4*)(smem + rawoff + m * 512 + j * 16);
                uint32_t h0, l0, h1, l1;
                split2(v.x, v.y, h0, l0);
                split2(v.z, v.w, h1, l1);
                uint32_t co = (uint32_t)(m * 272 + j * 8);
                *(uint2*)(smem + OF_CH + co) = make_uint2(h0, h1);
                *(uint2*)(smem + OF_CL + co) = make_uint2(l0, l1);
            }
        }
        __syncthreads();

        // ---- MMA: 8 k-steps x 4 m-tiles x 6 MMAs ----
        float acc[4][2][4];
#pragma unroll
        for (int mt = 0; mt < 4; mt++)
#pragma unroll
            for (int nt = 0; nt < 2; nt++)
#pragma unroll
                for (int q = 0; q < 4; q++) acc[mt][nt][q] = 0.f;

#pragma unroll
        for (int ks = 0; ks < 8; ks++) {
            const uint32_t ko = (uint32_t)ks * 32;
#pragma unroll
            for (int mt = 0; mt < 4; mt++) {
                uint32_t a0, a1, a2, a3;
                LDSM_X4(a0, a1, a2, a3, Ah + (uint32_t)(mt * 16 * 272) + ko);
                MMA_BF16(acc[mt][0], a0, a1, a2, a3, whf[ks * 2 + 0][0], whf[ks * 2 + 0][1]);
                MMA_BF16(acc[mt][1], a0, a1, a2, a3, whf[ks * 2 + 1][0], whf[ks * 2 + 1][1]);
                MMA_BF16(acc[mt][0], a0, a1, a2, a3, wlf[ks * 2 + 0][0], wlf[ks * 2 + 0][1]);
                MMA_BF16(acc[mt][1], a0, a1, a2, a3, wlf[ks * 2 + 1][0], wlf[ks * 2 + 1][1]);
                uint32_t c0, c1, c2, c3;
                LDSM_X4(c0, c1, c2, c3, Al + (uint32_t)(mt * 16 * 272) + ko);
                MMA_BF16(acc[mt][0], c0, c1, c2, c3, whf[ks * 2 + 0][0], whf[ks * 2 + 0][1]);
                MMA_BF16(acc[mt][1], c0, c1, c2, c3, whf[ks * 2 + 1][0], whf[ks * 2 + 1][1]);
            }
        }

        // ---- Epilogue: fp16 stores (+bias on B table) ----
        const int m0 = t * 64;
#pragma unroll
        for (int mt = 0; mt < 4; mt++) {
            int r0 = m0 + mt * 16 + (lane >> 2);
#pragma unroll
            for (int nt = 0; nt < 2; nt++) {
                float2 b = nt ? bb1 : bb0;
                int c = w * 16 + nt * 8 + (lane & 3) * 2;
                if (r0 < N)
                    *(half2*)(dsttab + (size_t)r0 * 128 + c) =
                        __floats2half2_rn(acc[mt][nt][0] + b.x, acc[mt][nt][1] + b.y);
                if (r0 + 8 < N)
                    *(half2*)(dsttab + (size_t)(r0 + 8) * 128 + c) =
                        __floats2half2_rn(acc[mt][nt][2] + b.x, acc[mt][nt][3] + b.y);
            }
        }
        it ^= 1;
    }
}

// ---------------------------------------------------------------------------
// Edge pass: out[e] = relu(A16[row] + B16[col]) . W2 + b2
// half2 add+relu (HADD2/HMAX2), fp32 dot. 16 lanes/edge, 2-pair unroll.
// ---------------------------------------------------------------------------
__device__ __forceinline__ float edge_dot(uint4 a4, uint4 b4,
                                          float4 w2a, float4 w2b) {
    const half2 z2 = __floats2half2_rn(0.f, 0.f);
    half2 h0 = __hmax2(__hadd2(*(half2*)&a4.x, *(half2*)&b4.x), z2);
    half2 h1 = __hmax2(__hadd2(*(half2*)&a4.y, *(half2*)&b4.y), z2);
    half2 h2 = __hmax2(__hadd2(*(half2*)&a4.z, *(half2*)&b4.z), z2);
    half2 h3 = __hmax2(__hadd2(*(half2*)&a4.w, *(half2*)&b4.w), z2);
    float2 f0 = __half22float2(h0);
    float2 f1 = __half22float2(h1);
    float2 f2 = __half22float2(h2);
    float2 f3 = __half22float2(h3);
    return f0.x * w2a.x + f0.y * w2a.y
         + f1.x * w2a.z + f1.y * w2a.w
         + f2.x * w2b.x + f2.y * w2b.y
         + f3.x * w2b.z + f3.y * w2b.w;
}

__global__ void __launch_bounds__(256)
edge_kernel(const void* __restrict__ ei_raw,
            const float* __restrict__ W2,
            const float* __restrict__ b2,
            float* __restrict__ out, int E, int N)
{
    const long long* ei64 = (const long long*)ei_raw;
    const int*       ei32 = (const int*)ei_raw;

    int is64 = 1;
#pragma unroll
    for (int i = 0; i < 8; i++) {
        long long v = __ldg(&ei64[i]);
        if (v < 0 || v >= (long long)N) is64 = 0;
    }

    const int lane = threadIdx.x & 31;
    const int sub = lane >> 4;     // which edge of the pair
    const int sl  = lane & 15;     // lane within edge

    const float4 w2a = ((const float4*)W2)[sl * 2];
    const float4 w2b = ((const float4*)W2)[sl * 2 + 1];
    const float b2v = __ldg(b2);

    const int warp = (blockIdx.x * 256 + threadIdx.x) >> 5;
    const int nwarp = (gridDim.x * 256) >> 5;
    const int npairs = (E + 1) >> 1;

    for (int p = warp; p < npairs; p += 2 * nwarp) {
        const int pB = p + nwarp;
        const int e1 = p * 2 + sub;
        const int e2 = pB * 2 + sub;
        const bool hasB = (pB < npairs) && (e2 < E);

        int r1, c1, r2 = 0, c2 = 0;
        if (is64) {
            r1 = (int)ei64[e1];  c1 = (int)ei64[E + e1];
            if (hasB) { r2 = (int)ei64[e2];  c2 = (int)ei64[E + e2]; }
        } else {
            r1 = ei32[e1];  c1 = ei32[E + e1];
            if (hasB) { r2 = ei32[e2];  c2 = ei32[E + e2]; }
        }

        uint4 a1 = *(const uint4*)(g_A16 + (size_t)r1 * 128 + sl * 8);
        uint4 b1 = *(const uint4*)(g_B16 + (size_t)c1 * 128 + sl * 8);
        uint4 a2 = make_uint4(0, 0, 0, 0), b2q = a2;
        if (hasB) {
            a2 = *(const uint4*)(g_A16 + (size_t)r2 * 128 + sl * 8);
            b2q = *(const uint4*)(g_B16 + (size_t)c2 * 128 + sl * 8);
        }

        float s1 = edge_dot(a1, b1, w2a, w2b);
        float s2 = edge_dot(a2, b2q, w2a, w2b);
#pragma unroll
        for (int o = 8; o; o >>= 1) {
            s1 += __shfl_xor_sync(0xffffffffu, s1, o);
            s2 += __shfl_xor_sync(0xffffffffu, s2, o);
        }

        if (sl == 0) {
            if (e1 < E) out[e1] = s1 + b2v;
            if (hasB)   out[e2] = s2 + b2v;
        }
    }
}

// ---------------------------------------------------------------------------
// Launch
// ---------------------------------------------------------------------------
extern "C" void kernel_launch(void* const* d_in, const int* in_sizes, int n_in,
                              void* d_out, int out_size)
{
    const float* z  = (const float*)d_in[0];
    const void*  ei = d_in[1];
    const float* W1 = (const float*)d_in[2];
    const float* b1 = (const float*)d_in[3];
    const float* W2 = (const float*)d_in[4];
    const float* b2 = (const float*)d_in[5];
    float* out = (float*)d_out;

    const int N = in_sizes[0] / D;   // 100000
    const int E = out_size;          // 800000

    cudaFuncSetAttribute(node_mma_kernel,
                         cudaFuncAttributeMaxDynamicSharedMemorySize, 100352);
    node_mma_kernel<<<296, 256, 100352>>>(z, W1, b1, N);

    edge_kernel<<<1184, 256>>>(ei, W2, b2, out, E, N);
}

// round 7
// speedup vs baseline: 2.7331x; 1.1364x over previous
#include <cuda_runtime.h>
#include <cuda_fp16.h>
#include <stdint.h>

#define D 128
#define NMAX 100000
#define WPITCH 136                   // fp16 elems per smem row (128 + 8 pad)
#define PITCHB 272                   // bytes

// ---------------------------------------------------------------------------
// Device scratch (static — no cudaMalloc allowed)
// ---------------------------------------------------------------------------
__device__ __align__(16) __half g_A16[(size_t)(NMAX + 128) * 128];  // z@W1[:128]
__device__ __align__(16) __half g_B16[(size_t)(NMAX + 128) * 128];  // z@W1[128:]+b1

// ---------------------------------------------------------------------------
// PTX helpers (sm_80-era only; safe on .target sm_103)
// ---------------------------------------------------------------------------
__device__ __forceinline__ uint32_t smem_u32(const void* p) {
    uint32_t a;
    asm("{ .reg .u64 t; cvta.to.shared.u64 t, %1; cvt.u32.u64 %0, t; }"
        : "=r"(a) : "l"(p));
    return a;
}

#define LDSM_X4(r0, r1, r2, r3, addr)                                           \
    asm volatile("ldmatrix.sync.aligned.m8n8.x4.shared.b16 {%0,%1,%2,%3},[%4];" \
                 : "=r"(r0), "=r"(r1), "=r"(r2), "=r"(r3) : "r"(addr))

#define LDSM_X2(r0, r1, addr)                                                \
    asm volatile("ldmatrix.sync.aligned.m8n8.x2.shared.b16 {%0,%1},[%2];"    \
                 : "=r"(r0), "=r"(r1) : "r"(addr))

#define MMA_F16(d, a0, a1, a2, a3, b0, b1)                                   \
    asm volatile("mma.sync.aligned.m16n8k16.row.col.f32.f16.f16.f32 "        \
                 "{%0,%1,%2,%3},{%4,%5,%6,%7},{%8,%9},{%0,%1,%2,%3};"        \
                 : "+f"((d)[0]), "+f"((d)[1]), "+f"((d)[2]), "+f"((d)[3])    \
                 : "r"(a0), "r"(a1), "r"(a2), "r"(a3), "r"(b0), "r"(b1))

#define CP_ASYNC16(dst, src)                                                 \
    asm volatile("cp.async.cg.shared.global [%0], [%1], 16;"                 \
                 :: "r"(dst), "l"(src))
#define CP_COMMIT() asm volatile("cp.async.commit_group;" ::: "memory")
#define CP_WAIT1()  asm volatile("cp.async.wait_group 1;" ::: "memory")

// ---------------------------------------------------------------------------
// Node projection via mma.sync fp16 (fp32 accum), 2-term W split:
//   D = zh@Wh + zh@Wl   (Wh+Wl captures W to ~2^-23; z fp16 err ~6e-5)
// 296 CTAs x 256 thr, 2 CTAs/SM. hb = bid&1 selects output table (A or B);
// 64-row tiles, stride 148. cp.async fp32 z (dbl-buffered) -> fp16 convert
// -> ldmatrix -> MMA with register-resident Wh/Wl fragments -> fp16 stores.
// SMEM: raw0 32K | raw1 32K | conv 17408 (+17408 W-staging scratch) = 100352 B
// ---------------------------------------------------------------------------
__global__ void __launch_bounds__(256, 2)
node_mma_kernel(const float* __restrict__ z, const float* __restrict__ W1,
                const float* __restrict__ b1, int N)
{
    extern __shared__ char smem[];
    const uint32_t OF_RAW0 = 0;
    const uint32_t OF_RAW1 = 32768;
    const uint32_t OF_CH   = 65536;            // conv (64 rows x 272B)

    const uint32_t sb = smem_u32(smem);
    const int tid = threadIdx.x;
    const int w = tid >> 5;
    const int lane = tid & 31;
    const int hb = blockIdx.x & 1;            // 0: A table, 1: B table
    const int tstart = blockIdx.x >> 1;       // 0..147
    const int ntiles = (N + 63) / 64;

    // ---- cp.async raw fp32 tile: 64 rows x 512 B (zero-fill OOB rows) ----
    auto issue_tile = [&](int t, uint32_t bufoff) {
        const char* src = (const char*)z + (size_t)t * 64 * 512;
        const int rows_valid = N - t * 64;
#pragma unroll
        for (int q = 0; q < 8; q++) {
            int idx = tid + q * 256;          // 0..2047
            int m = idx >> 5, j = idx & 31;
            uint32_t off = bufoff + (uint32_t)(m * 512 + j * 16);
            if (m < rows_valid)
                CP_ASYNC16(sb + off, src + m * 512 + j * 16);
            else
                *(float4*)(smem + off) = make_float4(0.f, 0.f, 0.f, 0.f);
        }
    };

    if (tstart < ntiles) issue_tile(tstart, OF_RAW0);
    CP_COMMIT();

    // ---- W1 -> fp16 hi/lo fragments in registers (16 cols per warp) ----
    // Staging scratch: 8 warps x 4352 B at OF_CH (used before main loop only)
    uint32_t whf[16][2], wlf[16][2];
    {
        const int n0 = w * 16;
        const uint32_t stg = (uint32_t)(OF_CH + w * 4352);
        const uint32_t boff = sb + stg
            + (uint32_t)((lane & 7) * 272 + ((lane >> 3) & 1) * 16);

#pragma unroll
        for (int q = 0; q < 64; q++) {        // 2048 elems / 32 lanes
            int idx = lane + q * 32;
            int r = idx & 15, k = idx >> 4;
            float x = W1[(size_t)(hb * 128 + k) * 128 + n0 + r];
            *(__half*)(smem + stg + r * 272 + k * 2) = __float2half_rn(x);
        }
        __syncwarp();
#pragma unroll
        for (int ks = 0; ks < 8; ks++)
#pragma unroll
            for (int nt = 0; nt < 2; nt++)
                LDSM_X2(whf[ks * 2 + nt][0], whf[ks * 2 + nt][1],
                        boff + (uint32_t)(nt * 8 * 272 + ks * 32));
        __syncwarp();
#pragma unroll
        for (int q = 0; q < 64; q++) {
            int idx = lane + q * 32;
            int r = idx & 15, k = idx >> 4;
            float x = W1[(size_t)(hb * 128 + k) * 128 + n0 + r];
            __half hi = __float2half_rn(x);
            __half lo = __float2half_rn(x - __half2float(hi));
            *(__half*)(smem + stg + r * 272 + k * 2) = lo;
        }
        __syncwarp();
#pragma unroll
        for (int ks = 0; ks < 8; ks++)
#pragma unroll
            for (int nt = 0; nt < 2; nt++)
                LDSM_X2(wlf[ks * 2 + nt][0], wlf[ks * 2 + nt][1],
                        boff + (uint32_t)(nt * 8 * 272 + ks * 32));
    }
    __syncthreads();   // staging free before main loop

    // Bias (B table only)
    float2 bb0 = make_float2(0.f, 0.f), bb1 = bb0;
    if (hb) {
        int c = w * 16 + (lane & 3) * 2;
        bb0 = *(const float2*)(b1 + c);
        bb1 = *(const float2*)(b1 + c + 8);
    }
    __half* dsttab = hb ? g_B16 : g_A16;

    const uint32_t a_off = (uint32_t)((lane & 15) * WPITCH + (lane >> 4) * 8) * 2;
    const uint32_t Ah = sb + OF_CH + a_off;

    int it = 0;
    for (int t = tstart; t < ntiles; t += 148) {
        int tn = t + 148;
        if (tn < ntiles) issue_tile(tn, it ? OF_RAW0 : OF_RAW1);
        CP_COMMIT();
        CP_WAIT1();
        __syncthreads();   // raw[it] ready; prior MMA reads of conv done

        // ---- convert raw fp32 -> fp16 (pitched for ldmatrix) ----
        {
            const uint32_t rawoff = it ? OF_RAW1 : OF_RAW0;
#pragma unroll
            for (int q = 0; q < 8; q++) {
                int idx = tid + q * 256;       // 0..2047
                int m = idx >> 5, j = idx & 31;
                float4 v = *(const float4*)(smem + rawoff + m * 512 + j * 16);
                half2 h0 = __floats2half2_rn(v.x, v.y);
                half2 h1 = __floats2half2_rn(v.z, v.w);
                *(uint2*)(smem + OF_CH + (uint32_t)(m * 272 + j * 8)) =
                    make_uint2(*(uint32_t*)&h0, *(uint32_t*)&h1);
            }
        }
        __syncthreads();

        // ---- MMA: 8 k-steps x 4 m-tiles x 4 MMAs (LDSM:MMA = 1:4) ----
        float acc[4][2][4];
#pragma unroll
        for (int mt = 0; mt < 4; mt++)
#pragma unroll
            for (int nt = 0; nt < 2; nt++)
#pragma unroll
                for (int q = 0; q < 4; q++) acc[mt][nt][q] = 0.f;

#pragma unroll
        for (int ks = 0; ks < 8; ks++) {
            const uint32_t ko = (uint32_t)ks * 32;
#pragma unroll
            for (int mt = 0; mt < 4; mt++) {
                uint32_t a0, a1, a2, a3;
                LDSM_X4(a0, a1, a2, a3, Ah + (uint32_t)(mt * 16 * 272) + ko);
                MMA_F16(acc[mt][0], a0, a1, a2, a3, whf[ks * 2 + 0][0], whf[ks * 2 + 0][1]);
                MMA_F16(acc[mt][1], a0, a1, a2, a3, whf[ks * 2 + 1][0], whf[ks * 2 + 1][1]);
                MMA_F16(acc[mt][0], a0, a1, a2, a3, wlf[ks * 2 + 0][0], wlf[ks * 2 + 0][1]);
                MMA_F16(acc[mt][1], a0, a1, a2, a3, wlf[ks * 2 + 1][0], wlf[ks * 2 + 1][1]);
            }
        }

        // ---- Epilogue: fp16 stores (+bias on B table) ----
        const int m0 = t * 64;
#pragma unroll
        for (int mt = 0; mt < 4; mt++) {
            int r0 = m0 + mt * 16 + (lane >> 2);
#pragma unroll
            for (int nt = 0; nt < 2; nt++) {
                float2 b = nt ? bb1 : bb0;
                int c = w * 16 + nt * 8 + (lane & 3) * 2;
                if (r0 < N)
                    *(half2*)(dsttab + (size_t)r0 * 128 + c) =
                        __floats2half2_rn(acc[mt][nt][0] + b.x, acc[mt][nt][1] + b.y);
                if (r0 + 8 < N)
                    *(half2*)(dsttab + (size_t)(r0 + 8) * 128 + c) =
                        __floats2half2_rn(acc[mt][nt][2] + b.x, acc[mt][nt][3] + b.y);
            }
        }
        it ^= 1;
    }
}

// ---------------------------------------------------------------------------
// Edge pass: out[e] = relu(A16[row] + B16[col]) . W2 + b2
// Packed fp16: HADD2+HMAX2 then HFMA2 dot (two length-2 chains per lane),
// fp32 cross-lane reduce. 16 lanes/edge, 2-pair unroll.
// ---------------------------------------------------------------------------
__device__ __forceinline__ float edge_dot(uint4 a4, uint4 b4,
                                          half2 w0, half2 w1,
                                          half2 w2, half2 w3) {
    const half2 z2 = __floats2half2_rn(0.f, 0.f);
    half2 h0 = __hmax2(__hadd2(*(half2*)&a4.x, *(half2*)&b4.x), z2);
    half2 h1 = __hmax2(__hadd2(*(half2*)&a4.y, *(half2*)&b4.y), z2);
    half2 h2 = __hmax2(__hadd2(*(half2*)&a4.z, *(half2*)&b4.z), z2);
    half2 h3 = __hmax2(__hadd2(*(half2*)&a4.w, *(half2*)&b4.w), z2);
    half2 acc0 = __hfma2(h2, w2, __hmul2(h0, w0));
    half2 acc1 = __hfma2(h3, w3, __hmul2(h1, w1));
    float2 f0 = __half22float2(acc0);
    float2 f1 = __half22float2(acc1);
    return (f0.x + f0.y) + (f1.x + f1.y);
}

__global__ void __launch_bounds__(256)
edge_kernel(const void* __restrict__ ei_raw,
            const float* __restrict__ W2,
            const float* __restrict__ b2,
            float* __restrict__ out, int E, int N)
{
    const long long* ei64 = (const long long*)ei_raw;
    const int*       ei32 = (const int*)ei_raw;

    int is64 = 1;
#pragma unroll
    for (int i = 0; i < 8; i++) {
        long long v = __ldg(&ei64[i]);
        if (v < 0 || v >= (long long)N) is64 = 0;
    }

    const int lane = threadIdx.x & 31;
    const int sub = lane >> 4;     // which edge of the pair
    const int sl  = lane & 15;     // lane within edge (8 dims)

    const int cw = sl * 8;
    const half2 w0 = __floats2half2_rn(W2[cw + 0], W2[cw + 1]);
    const half2 w1 = __floats2half2_rn(W2[cw + 2], W2[cw + 3]);
    const half2 w2 = __floats2half2_rn(W2[cw + 4], W2[cw + 5]);
    const half2 w3 = __floats2half2_rn(W2[cw + 6], W2[cw + 7]);
    const float b2v = __ldg(b2);

    const int warp = (blockIdx.x * 256 + threadIdx.x) >> 5;
    const int nwarp = (gridDim.x * 256) >> 5;
    const int npairs = (E + 1) >> 1;

    for (int p = warp; p < npairs; p += 2 * nwarp) {
        const int pB = p + nwarp;
        const int e1 = p * 2 + sub;
        const int e2 = pB * 2 + sub;
        const bool hasB = (pB < npairs) && (e2 < E);

        int r1, c1, r2 = 0, c2 = 0;
        if (is64) {
            r1 = (int)ei64[e1];  c1 = (int)ei64[E + e1];
            if (hasB) { r2 = (int)ei64[e2];  c2 = (int)ei64[E + e2]; }
        } else {
            r1 = ei32[e1];  c1 = ei32[E + e1];
            if (hasB) { r2 = ei32[e2];  c2 = ei32[E + e2]; }
        }

        uint4 a1 = *(const uint4*)(g_A16 + (size_t)r1 * 128 + sl * 8);
        uint4 b1 = *(const uint4*)(g_B16 + (size_t)c1 * 128 + sl * 8);
        uint4 a2 = make_uint4(0, 0, 0, 0), b2q = a2;
        if (hasB) {
            a2 = *(const uint4*)(g_A16 + (size_t)r2 * 128 + sl * 8);
            b2q = *(const uint4*)(g_B16 + (size_t)c2 * 128 + sl * 8);
        }

        float s1 = edge_dot(a1, b1, w0, w1, w2, w3);
        float s2 = edge_dot(a2, b2q, w0, w1, w2, w3);
#pragma unroll
        for (int o = 8; o; o >>= 1) {
            s1 += __shfl_xor_sync(0xffffffffu, s1, o);
            s2 += __shfl_xor_sync(0xffffffffu, s2, o);
        }

        if (sl == 0) {
            if (e1 < E) out[e1] = s1 + b2v;
            if (hasB)   out[e2] = s2 + b2v;
        }
    }
}

// ---------------------------------------------------------------------------
// Launch
// ---------------------------------------------------------------------------
extern "C" void kernel_launch(void* const* d_in, const int* in_sizes, int n_in,
                              void* d_out, int out_size)
{
    const float* z  = (const float*)d_in[0];
    const void*  ei = d_in[1];
    const float* W1 = (const float*)d_in[2];
    const float* b1 = (const float*)d_in[3];
    const float* W2 = (const float*)d_in[4];
    const float* b2 = (const float*)d_in[5];
    float* out = (float*)d_out;

    const int N = in_sizes[0] / D;   // 100000
    const int E = out_size;          // 800000

    cudaFuncSetAttribute(node_mma_kernel,
                         cudaFuncAttributeMaxDynamicSharedMemorySize, 100352);
    node_mma_kernel<<<296, 256, 100352>>>(z, W1, b1, N);

    edge_kernel<<<1184, 256>>>(ei, W2, b2, out, E, N);
}

// round 8
// speedup vs baseline: 3.2165x; 1.1769x over previous
#include <cuda_runtime.h>
#include <cuda_fp16.h>
#include <stdint.h>

#define D 128
#define NMAX 100000
#define WPITCH 136                   // fp16 elems per smem row (128 + 8 pad)
#define PITCHB 272                   // bytes

// ---------------------------------------------------------------------------
// Device scratch (static — no cudaMalloc allowed)
// ---------------------------------------------------------------------------
__device__ __align__(16) __half g_A16[(size_t)(NMAX + 128) * 128];  // z@W1[:128]
__device__ __align__(16) __half g_B16[(size_t)(NMAX + 128) * 128];  // z@W1[128:]+b1

// ---------------------------------------------------------------------------
// PTX helpers (sm_80-era only; safe on .target sm_103)
// ---------------------------------------------------------------------------
__device__ __forceinline__ uint32_t smem_u32(const void* p) {
    uint32_t a;
    asm("{ .reg .u64 t; cvta.to.shared.u64 t, %1; cvt.u32.u64 %0, t; }"
        : "=r"(a) : "l"(p));
    return a;
}

#define LDSM_X4(r0, r1, r2, r3, addr)                                           \
    asm volatile("ldmatrix.sync.aligned.m8n8.x4.shared.b16 {%0,%1,%2,%3},[%4];" \
                 : "=r"(r0), "=r"(r1), "=r"(r2), "=r"(r3) : "r"(addr))

#define LDSM_X2(r0, r1, addr)                                                \
    asm volatile("ldmatrix.sync.aligned.m8n8.x2.shared.b16 {%0,%1},[%2];"    \
                 : "=r"(r0), "=r"(r1) : "r"(addr))

#define MMA_F16(d, a0, a1, a2, a3, b0, b1)                                   \
    asm volatile("mma.sync.aligned.m16n8k16.row.col.f32.f16.f16.f32 "        \
                 "{%0,%1,%2,%3},{%4,%5,%6,%7},{%8,%9},{%0,%1,%2,%3};"        \
                 : "+f"((d)[0]), "+f"((d)[1]), "+f"((d)[2]), "+f"((d)[3])    \
                 : "r"(a0), "r"(a1), "r"(a2), "r"(a3), "r"(b0), "r"(b1))

#define CP_ASYNC16(dst, src)                                                 \
    asm volatile("cp.async.cg.shared.global [%0], [%1], 16;"                 \
                 :: "r"(dst), "l"(src))
#define CP_COMMIT() asm volatile("cp.async.commit_group;" ::: "memory")
#define CP_WAIT1()  asm volatile("cp.async.wait_group 1;" ::: "memory")

// ---------------------------------------------------------------------------
// Node projection via mma.sync fp16 (fp32 accum), single pass:
//   A = z16 @ W16[:128],  B = z16 @ W16[128:] + b1
// 296 CTAs x 256 thr, 2 CTAs/SM. hb = bid&1 selects output table (A or B);
// 64-row tiles, stride 148. cp.async fp32 z (dbl-buffered) -> fp16 convert
// -> ldmatrix -> MMA with register-resident W fragments -> fp16 stores.
// SMEM: raw0 32K | raw1 32K | conv 17408 (doubles as W staging) = 82944 B
// ---------------------------------------------------------------------------
__global__ void __launch_bounds__(256, 2)
node_mma_kernel(const float* __restrict__ z, const float* __restrict__ W1,
                const float* __restrict__ b1, int N)
{
    extern __shared__ char smem[];
    const uint32_t OF_RAW0 = 0;
    const uint32_t OF_RAW1 = 32768;
    const uint32_t OF_CH   = 65536;            // conv (64 rows x 272B)

    const uint32_t sb = smem_u32(smem);
    const int tid = threadIdx.x;
    const int w = tid >> 5;
    const int lane = tid & 31;
    const int hb = blockIdx.x & 1;            // 0: A table, 1: B table
    const int tstart = blockIdx.x >> 1;       // 0..147
    const int ntiles = (N + 63) / 64;

    // ---- cp.async raw fp32 tile: 64 rows x 512 B (zero-fill OOB rows) ----
    auto issue_tile = [&](int t, uint32_t bufoff) {
        const char* src = (const char*)z + (size_t)t * 64 * 512;
        const int rows_valid = N - t * 64;
#pragma unroll
        for (int q = 0; q < 8; q++) {
            int idx = tid + q * 256;          // 0..2047
            int m = idx >> 5, j = idx & 31;
            uint32_t off = bufoff + (uint32_t)(m * 512 + j * 16);
            if (m < rows_valid)
                CP_ASYNC16(sb + off, src + m * 512 + j * 16);
            else
                *(float4*)(smem + off) = make_float4(0.f, 0.f, 0.f, 0.f);
        }
    };

    if (tstart < ntiles) issue_tile(tstart, OF_RAW0);
    CP_COMMIT();

    // ---- W1 -> fp16 fragments in registers (16 cols per warp) ----
    // Staging scratch: 8 warps x 2176 B within conv region
    uint32_t whf[16][2];
    {
        const int n0 = w * 16;
        const uint32_t stg = (uint32_t)(OF_CH + w * 2176);   // 8 rows x 272B
        // stage columns n0..n0+15 as [r][k] with r = col-in-slice
#pragma unroll
        for (int q = 0; q < 64; q++) {        // 2048 elems / 32 lanes
            int idx = lane + q * 32;
            int r = idx & 15, k = idx >> 4;
            float x = W1[(size_t)(hb * 128 + k) * 128 + n0 + r];
            // two 8-row groups share staging: rows 0-7 then 8-15 at +136B? 
            // simpler: full 16 rows x 272B needs 4352B; use 2 passes of 8 rows
            (void)x;
        }
        // two-pass staging: rows 0-7, then rows 8-15 (scratch = 8 rows)
        const uint32_t boff = sb + stg
            + (uint32_t)((lane & 7) * 272 + ((lane >> 3) & 1) * 16);
#pragma unroll
        for (int half8 = 0; half8 < 2; half8++) {
#pragma unroll
            for (int q = 0; q < 32; q++) {    // 8 rows x 128 k / 32 lanes
                int idx = lane + q * 32;
                int r = idx & 7, k = idx >> 3;
                float x = W1[(size_t)(hb * 128 + k) * 128 + n0 + half8 * 8 + r];
                *(__half*)(smem + stg + r * 272 + k * 2) = __float2half_rn(x);
            }
            __syncwarp();
#pragma unroll
            for (int ks = 0; ks < 8; ks++)
                LDSM_X2(whf[ks * 2 + half8][0], whf[ks * 2 + half8][1],
                        boff + (uint32_t)(ks * 32));
            __syncwarp();
        }
    }
    __syncthreads();   // staging free before main loop

    // Bias (B table only)
    float2 bb0 = make_float2(0.f, 0.f), bb1 = bb0;
    if (hb) {
        int c = w * 16 + (lane & 3) * 2;
        bb0 = *(const float2*)(b1 + c);
        bb1 = *(const float2*)(b1 + c + 8);
    }
    __half* dsttab = hb ? g_B16 : g_A16;

    const uint32_t a_off = (uint32_t)((lane & 15) * WPITCH + (lane >> 4) * 8) * 2;
    const uint32_t Ah = sb + OF_CH + a_off;

    int it = 0;
    for (int t = tstart; t < ntiles; t += 148) {
        int tn = t + 148;
        if (tn < ntiles) issue_tile(tn, it ? OF_RAW0 : OF_RAW1);
        CP_COMMIT();
        CP_WAIT1();
        __syncthreads();   // raw[it] ready; prior MMA reads of conv done

        // ---- convert raw fp32 -> fp16 (pitched for ldmatrix) ----
        {
            const uint32_t rawoff = it ? OF_RAW1 : OF_RAW0;
#pragma unroll
            for (int q = 0; q < 8; q++) {
                int idx = tid + q * 256;       // 0..2047
                int m = idx >> 5, j = idx & 31;
                float4 v = *(const float4*)(smem + rawoff + m * 512 + j * 16);
                half2 h0 = __floats2half2_rn(v.x, v.y);
                half2 h1 = __floats2half2_rn(v.z, v.w);
                *(uint2*)(smem + OF_CH + (uint32_t)(m * 272 + j * 8)) =
                    make_uint2(*(uint32_t*)&h0, *(uint32_t*)&h1);
            }
        }
        __syncthreads();

        // ---- MMA: 8 k-steps x 4 m-tiles x 2 MMAs (LDSM:MMA = 1:2) ----
        float acc[4][2][4];
#pragma unroll
        for (int mt = 0; mt < 4; mt++)
#pragma unroll
            for (int nt = 0; nt < 2; nt++)
#pragma unroll
                for (int q = 0; q < 4; q++) acc[mt][nt][q] = 0.f;

#pragma unroll
        for (int ks = 0; ks < 8; ks++) {
            const uint32_t ko = (uint32_t)ks * 32;
#pragma unroll
            for (int mt = 0; mt < 4; mt++) {
                uint32_t a0, a1, a2, a3;
                LDSM_X4(a0, a1, a2, a3, Ah + (uint32_t)(mt * 16 * 272) + ko);
                MMA_F16(acc[mt][0], a0, a1, a2, a3, whf[ks * 2 + 0][0], whf[ks * 2 + 0][1]);
                MMA_F16(acc[mt][1], a0, a1, a2, a3, whf[ks * 2 + 1][0], whf[ks * 2 + 1][1]);
            }
        }

        // ---- Epilogue: fp16 stores (+bias on B table) ----
        const int m0 = t * 64;
#pragma unroll
        for (int mt = 0; mt < 4; mt++) {
            int r0 = m0 + mt * 16 + (lane >> 2);
#pragma unroll
            for (int nt = 0; nt < 2; nt++) {
                float2 b = nt ? bb1 : bb0;
                int c = w * 16 + nt * 8 + (lane & 3) * 2;
                if (r0 < N)
                    *(half2*)(dsttab + (size_t)r0 * 128 + c) =
                        __floats2half2_rn(acc[mt][nt][0] + b.x, acc[mt][nt][1] + b.y);
                if (r0 + 8 < N)
                    *(half2*)(dsttab + (size_t)(r0 + 8) * 128 + c) =
                        __floats2half2_rn(acc[mt][nt][2] + b.x, acc[mt][nt][3] + b.y);
            }
        }
        it ^= 1;
    }
}

// ---------------------------------------------------------------------------
// Edge pass: out[e] = relu(A16[row] + B16[col]) . W2 + b2
// HADD2+HMAX2 add/relu, fp32 dot (precision). 16 lanes/edge, 2-pair unroll.
// L2-bandwidth-bound: instruction mix is free here.
// ---------------------------------------------------------------------------
__device__ __forceinline__ float edge_dot(uint4 a4, uint4 b4,
                                          float4 w2a, float4 w2b) {
    const half2 z2 = __floats2half2_rn(0.f, 0.f);
    half2 h0 = __hmax2(__hadd2(*(half2*)&a4.x, *(half2*)&b4.x), z2);
    half2 h1 = __hmax2(__hadd2(*(half2*)&a4.y, *(half2*)&b4.y), z2);
    half2 h2 = __hmax2(__hadd2(*(half2*)&a4.z, *(half2*)&b4.z), z2);
    half2 h3 = __hmax2(__hadd2(*(half2*)&a4.w, *(half2*)&b4.w), z2);
    float2 f0 = __half22float2(h0);
    float2 f1 = __half22float2(h1);
    float2 f2 = __half22float2(h2);
    float2 f3 = __half22float2(h3);
    return f0.x * w2a.x + f0.y * w2a.y
         + f1.x * w2a.z + f1.y * w2a.w
         + f2.x * w2b.x + f2.y * w2b.y
         + f3.x * w2b.z + f3.y * w2b.w;
}

__global__ void __launch_bounds__(256)
edge_kernel(const void* __restrict__ ei_raw,
            const float* __restrict__ W2,
            const float* __restrict__ b2,
            float* __restrict__ out, int E, int N)
{
    const long long* ei64 = (const long long*)ei_raw;
    const int*       ei32 = (const int*)ei_raw;

    int is64 = 1;
#pragma unroll
    for (int i = 0; i < 8; i++) {
        long long v = __ldg(&ei64[i]);
        if (v < 0 || v >= (long long)N) is64 = 0;
    }

    const int lane = threadIdx.x & 31;
    const int sub = lane >> 4;     // which edge of the pair
    const int sl  = lane & 15;     // lane within edge (8 dims)

    const float4 w2a = ((const float4*)W2)[sl * 2];
    const float4 w2b = ((const float4*)W2)[sl * 2 + 1];
    const float b2v = __ldg(b2);

    const int warp = (blockIdx.x * 256 + threadIdx.x) >> 5;
    const int nwarp = (gridDim.x * 256) >> 5;
    const int npairs = (E + 1) >> 1;

    for (int p = warp; p < npairs; p += 2 * nwarp) {
        const int pB = p + nwarp;
        const int e1 = p * 2 + sub;
        const int e2 = pB * 2 + sub;
        const bool hasB = (pB < npairs) && (e2 < E);

        int r1, c1, r2 = 0, c2 = 0;
        if (is64) {
            r1 = (int)ei64[e1];  c1 = (int)ei64[E + e1];
            if (hasB) { r2 = (int)ei64[e2];  c2 = (int)ei64[E + e2]; }
        } else {
            r1 = ei32[e1];  c1 = ei32[E + e1];
            if (hasB) { r2 = ei32[e2];  c2 = ei32[E + e2]; }
        }

        uint4 a1 = *(const uint4*)(g_A16 + (size_t)r1 * 128 + sl * 8);
        uint4 b1 = *(const uint4*)(g_B16 + (size_t)c1 * 128 + sl * 8);
        uint4 a2 = make_uint4(0, 0, 0, 0), b2q = a2;
        if (hasB) {
            a2 = *(const uint4*)(g_A16 + (size_t)r2 * 128 + sl * 8);
            b2q = *(const uint4*)(g_B16 + (size_t)c2 * 128 + sl * 8);
        }

        float s1 = edge_dot(a1, b1, w2a, w2b);
        float s2 = edge_dot(a2, b2q, w2a, w2b);
#pragma unroll
        for (int o = 8; o; o >>= 1) {
            s1 += __shfl_xor_sync(0xffffffffu, s1, o);
            s2 += __shfl_xor_sync(0xffffffffu, s2, o);
        }

        if (sl == 0) {
            if (e1 < E) out[e1] = s1 + b2v;
            if (hasB)   out[e2] = s2 + b2v;
        }
    }
}

// ---------------------------------------------------------------------------
// Launch
// ---------------------------------------------------------------------------
extern "C" void kernel_launch(void* const* d_in, const int* in_sizes, int n_in,
                              void* d_out, int out_size)
{
    const float* z  = (const float*)d_in[0];
    const void*  ei = d_in[1];
    const float* W1 = (const float*)d_in[2];
    const float* b1 = (const float*)d_in[3];
    const float* W2 = (const float*)d_in[4];
    const float* b2 = (const float*)d_in[5];
    float* out = (float*)d_out;

    const int N = in_sizes[0] / D;   // 100000
    const int E = out_size;          // 800000

    cudaFuncSetAttribute(node_mma_kernel,
                         cudaFuncAttributeMaxDynamicSharedMemorySize, 82944);
    node_mma_kernel<<<296, 256, 82944>>>(z, W1, b1, N);

    edge_kernel<<<1184, 256>>>(ei, W2, b2, out, E, N);
}

// round 9
// speedup vs baseline: 3.7002x; 1.1504x over previous
#include <cuda_runtime.h>
#include <cuda_fp16.h>
#include <stdint.h>

#define D 128
#define NMAX 100000
#define WPITCH 136                   // fp16 elems per smem row (128 + 8 pad)
#define PITCHB 272                   // bytes

// ---------------------------------------------------------------------------
// Device scratch (static — no cudaMalloc allowed)
// ---------------------------------------------------------------------------
__device__ __align__(16) __half g_A16[(size_t)(NMAX + 128) * 128];  // z@W1[:128]
__device__ __align__(16) __half g_B16[(size_t)(NMAX + 128) * 128];  // z@W1[128:]+b1

// ---------------------------------------------------------------------------
// PTX helpers (sm_80-era only; safe on .target sm_103)
// ---------------------------------------------------------------------------
__device__ __forceinline__ uint32_t smem_u32(const void* p) {
    uint32_t a;
    asm("{ .reg .u64 t; cvta.to.shared.u64 t, %1; cvt.u32.u64 %0, t; }"
        : "=r"(a) : "l"(p));
    return a;
}

#define LDSM_X4(r0, r1, r2, r3, addr)                                           \
    asm volatile("ldmatrix.sync.aligned.m8n8.x4.shared.b16 {%0,%1,%2,%3},[%4];" \
                 : "=r"(r0), "=r"(r1), "=r"(r2), "=r"(r3) : "r"(addr))

#define LDSM_X2(r0, r1, addr)                                                \
    asm volatile("ldmatrix.sync.aligned.m8n8.x2.shared.b16 {%0,%1},[%2];"    \
                 : "=r"(r0), "=r"(r1) : "r"(addr))

#define MMA_F16(d, a0, a1, a2, a3, b0, b1)                                   \
    asm volatile("mma.sync.aligned.m16n8k16.row.col.f32.f16.f16.f32 "        \
                 "{%0,%1,%2,%3},{%4,%5,%6,%7},{%8,%9},{%0,%1,%2,%3};"        \
                 : "+f"((d)[0]), "+f"((d)[1]), "+f"((d)[2]), "+f"((d)[3])    \
                 : "r"(a0), "r"(a1), "r"(a2), "r"(a3), "r"(b0), "r"(b1))

// ---------------------------------------------------------------------------
// Node projection via mma.sync fp16 (fp32 accum), single pass:
//   A = z16 @ W16[:128],  B = z16 @ W16[128:] + b1
// 296 CTAs x 256 thr, 2 CTAs/SM. hb = bid&1 selects table; 64-row tiles,
// stride 148. Register-staged LDG pipeline (no raw smem round trip);
// smem-staged coalesced epilogue (full-sector STG.128).
// SMEM: conv0 17408 | conv1 17408 | epi 17408 = 52224 B
// ---------------------------------------------------------------------------
__global__ void __launch_bounds__(256, 2)
node_mma_kernel(const float* __restrict__ z, const float* __restrict__ W1,
                const float* __restrict__ b1, int N)
{
    extern __shared__ char smem[];
    const uint32_t OF_C0  = 0;
    const uint32_t OF_C1  = 17408;
    const uint32_t OF_EPI = 34816;

    const uint32_t sb = smem_u32(smem);
    const int tid = threadIdx.x;
    const int w = tid >> 5;
    const int lane = tid & 31;
    const int hb = blockIdx.x & 1;            // 0: A table, 1: B table
    const int tstart = blockIdx.x >> 1;       // 0..147
    const int ntiles = (N + 63) / 64;

    // per-thread raw-z staging mapping: idx = tid + q*256 -> (m, j)
    // m = idx>>5 in [0,64), j = idx&31 (float4 col)
    float4 rawreg[8];

    auto issue_ldg = [&](int t) {
        const int rows_valid = N - t * 64;
        const float4* src = (const float4*)(z + (size_t)t * 64 * 128);
#pragma unroll
        for (int q = 0; q < 8; q++) {
            int idx = tid + q * 256;
            int m = idx >> 5, j = idx & 31;
            rawreg[q] = (m < rows_valid) ? src[m * 32 + j]
                                         : make_float4(0.f, 0.f, 0.f, 0.f);
        }
    };

    auto cvt_sts = [&](uint32_t convoff) {
#pragma unroll
        for (int q = 0; q < 8; q++) {
            int idx = tid + q * 256;
            int m = idx >> 5, j = idx & 31;
            half2 h0 = __floats2half2_rn(rawreg[q].x, rawreg[q].y);
            half2 h1 = __floats2half2_rn(rawreg[q].z, rawreg[q].w);
            *(uint2*)(smem + convoff + (uint32_t)(m * 272 + j * 8)) =
                make_uint2(*(uint32_t*)&h0, *(uint32_t*)&h1);
        }
    };

    if (tstart < ntiles) issue_ldg(tstart);

    // ---- W1 -> fp16 fragments in registers (16 cols per warp) ----
    // Staging scratch: 8 warps x 2176 B within conv0 (pre-loop only)
    uint32_t whf[16][2];
    {
        const int n0 = w * 16;
        const uint32_t stg = (uint32_t)(OF_C0 + w * 2176);   // 8 rows x 272B
        const uint32_t boff = sb + stg
            + (uint32_t)((lane & 7) * 272 + ((lane >> 3) & 1) * 16);
#pragma unroll
        for (int half8 = 0; half8 < 2; half8++) {
#pragma unroll
            for (int q = 0; q < 32; q++) {    // 8 rows x 128 k / 32 lanes
                int idx = lane + q * 32;
                int r = idx & 7, k = idx >> 3;
                float x = W1[(size_t)(hb * 128 + k) * 128 + n0 + half8 * 8 + r];
                *(__half*)(smem + stg + r * 272 + k * 2) = __float2half_rn(x);
            }
            __syncwarp();
#pragma unroll
            for (int ks = 0; ks < 8; ks++)
                LDSM_X2(whf[ks * 2 + half8][0], whf[ks * 2 + half8][1],
                        boff + (uint32_t)(ks * 32));
            __syncwarp();
        }
    }
    __syncthreads();   // W scratch (conv0) free

    // prologue: convert first tile into conv0
    if (tstart < ntiles) cvt_sts(OF_C0);

    // Bias (B table only)
    float2 bb0 = make_float2(0.f, 0.f), bb1 = bb0;
    if (hb) {
        int c = w * 16 + (lane & 3) * 2;
        bb0 = *(const float2*)(b1 + c);
        bb1 = *(const float2*)(b1 + c + 8);
    }
    __half* dsttab = hb ? g_B16 : g_A16;

    const uint32_t a_off = (uint32_t)((lane & 15) * WPITCH + (lane >> 4) * 8) * 2;
    const uint32_t Ah = sb + OF_C0 + a_off;   // + it*17408

    int it = 0;
    for (int t = tstart; t < ntiles; t += 148) {
        const int tn = t + 148;

        __syncthreads();   // conv[it] STS visible; epi STG of prev iter done

        if (tn < ntiles) issue_ldg(tn);   // hidden under MMA + epilogue

        // ---- MMA: 8 k-steps x 4 m-tiles x 2 MMAs ----
        float acc[4][2][4];
#pragma unroll
        for (int mt = 0; mt < 4; mt++)
#pragma unroll
            for (int nt = 0; nt < 2; nt++)
#pragma unroll
                for (int q = 0; q < 4; q++) acc[mt][nt][q] = 0.f;

        const uint32_t Abase = Ah + (uint32_t)(it * 17408);
#pragma unroll
        for (int ks = 0; ks < 8; ks++) {
            const uint32_t ko = (uint32_t)ks * 32;
#pragma unroll
            for (int mt = 0; mt < 4; mt++) {
                uint32_t a0, a1, a2, a3;
                LDSM_X4(a0, a1, a2, a3, Abase + (uint32_t)(mt * 16 * 272) + ko);
                MMA_F16(acc[mt][0], a0, a1, a2, a3, whf[ks * 2 + 0][0], whf[ks * 2 + 0][1]);
                MMA_F16(acc[mt][1], a0, a1, a2, a3, whf[ks * 2 + 1][0], whf[ks * 2 + 1][1]);
            }
        }

        // ---- Epilogue: acc -> epi smem (conflict-free, pitch 272) ----
#pragma unroll
        for (int mt = 0; mt < 4; mt++) {
            int r = mt * 16 + (lane >> 2);
#pragma unroll
            for (int nt = 0; nt < 2; nt++) {
                float2 b = nt ? bb1 : bb0;
                uint32_t cbyte = (uint32_t)((w * 16 + nt * 8 + (lane & 3) * 2) * 2);
                half2 v0 = __floats2half2_rn(acc[mt][nt][0] + b.x, acc[mt][nt][1] + b.y);
                half2 v1 = __floats2half2_rn(acc[mt][nt][2] + b.x, acc[mt][nt][3] + b.y);
                *(half2*)(smem + OF_EPI + (uint32_t)r * 272 + cbyte) = v0;
                *(half2*)(smem + OF_EPI + (uint32_t)(r + 8) * 272 + cbyte) = v1;
            }
        }
        __syncthreads();

        // ---- Coalesced STG.128: 64 rows x 256 B ----
        {
            const int m0 = t * 64;
            const int rows_valid = N - m0;
#pragma unroll
            for (int p = 0; p < 4; p++) {
                int linear = p * 4096 + tid * 16;
                int row = linear >> 8;
                int cb = linear & 255;
                if (row < rows_valid)
                    *(uint4*)(dsttab + (size_t)(m0 + row) * 128 + (cb >> 1)) =
                        *(const uint4*)(smem + OF_EPI + row * 272 + cb);
            }
        }

        // ---- convert next tile into the other conv buffer ----
        if (tn < ntiles) cvt_sts(it ? OF_C0 : OF_C1);
        it ^= 1;
    }
}

// ---------------------------------------------------------------------------
// Edge pass: out[e] = relu(A16[row] + B16[col]) . W2 + b2
// HADD2+HMAX2 add/relu, fp32 dot. 16 lanes/edge, 2-pair unroll.
// At the LTS throughput cap (~10.6 TB/s L2 service) — leave alone.
// ---------------------------------------------------------------------------
__device__ __forceinline__ float edge_dot(uint4 a4, uint4 b4,
                                          float4 w2a, float4 w2b) {
    const half2 z2 = __floats2half2_rn(0.f, 0.f);
    half2 h0 = __hmax2(__hadd2(*(half2*)&a4.x, *(half2*)&b4.x), z2);
    half2 h1 = __hmax2(__hadd2(*(half2*)&a4.y, *(half2*)&b4.y), z2);
    half2 h2 = __hmax2(__hadd2(*(half2*)&a4.z, *(half2*)&b4.z), z2);
    half2 h3 = __hmax2(__hadd2(*(half2*)&a4.w, *(half2*)&b4.w), z2);
    float2 f0 = __half22float2(h0);
    float2 f1 = __half22float2(h1);
    float2 f2 = __half22float2(h2);
    float2 f3 = __half22float2(h3);
    return f0.x * w2a.x + f0.y * w2a.y
         + f1.x * w2a.z + f1.y * w2a.w
         + f2.x * w2b.x + f2.y * w2b.y
         + f3.x * w2b.z + f3.y * w2b.w;
}

__global__ void __launch_bounds__(256)
edge_kernel(const void* __restrict__ ei_raw,
            const float* __restrict__ W2,
            const float* __restrict__ b2,
            float* __restrict__ out, int E, int N)
{
    const long long* ei64 = (const long long*)ei_raw;
    const int*       ei32 = (const int*)ei_raw;

    int is64 = 1;
#pragma unroll
    for (int i = 0; i < 8; i++) {
        long long v = __ldg(&ei64[i]);
        if (v < 0 || v >= (long long)N) is64 = 0;
    }

    const int lane = threadIdx.x & 31;
    const int sub = lane >> 4;     // which edge of the pair
    const int sl  = lane & 15;     // lane within edge (8 dims)

    const float4 w2a = ((const float4*)W2)[sl * 2];
    const float4 w2b = ((const float4*)W2)[sl * 2 + 1];
    const float b2v = __ldg(b2);

    const int warp = (blockIdx.x * 256 + threadIdx.x) >> 5;
    const int nwarp = (gridDim.x * 256) >> 5;
    const int npairs = (E + 1) >> 1;

    for (int p = warp; p < npairs; p += 2 * nwarp) {
        const int pB = p + nwarp;
        const int e1 = p * 2 + sub;
        const int e2 = pB * 2 + sub;
        const bool hasB = (pB < npairs) && (e2 < E);

        int r1, c1, r2 = 0, c2 = 0;
        if (is64) {
            r1 = (int)ei64[e1];  c1 = (int)ei64[E + e1];
            if (hasB) { r2 = (int)ei64[e2];  c2 = (int)ei64[E + e2]; }
        } else {
            r1 = ei32[e1];  c1 = ei32[E + e1];
            if (hasB) { r2 = ei32[e2];  c2 = ei32[E + e2]; }
        }

        uint4 a1 = *(const uint4*)(g_A16 + (size_t)r1 * 128 + sl * 8);
        uint4 b1 = *(const uint4*)(g_B16 + (size_t)c1 * 128 + sl * 8);
        uint4 a2 = make_uint4(0, 0, 0, 0), b2q = a2;
        if (hasB) {
            a2 = *(const uint4*)(g_A16 + (size_t)r2 * 128 + sl * 8);
            b2q = *(const uint4*)(g_B16 + (size_t)c2 * 128 + sl * 8);
        }

        float s1 = edge_dot(a1, b1, w2a, w2b);
        float s2 = edge_dot(a2, b2q, w2a, w2b);
#pragma unroll
        for (int o = 8; o; o >>= 1) {
            s1 += __shfl_xor_sync(0xffffffffu, s1, o);
            s2 += __shfl_xor_sync(0xffffffffu, s2, o);
        }

        if (sl == 0) {
            if (e1 < E) out[e1] = s1 + b2v;
            if (hasB)   out[e2] = s2 + b2v;
        }
    }
}

// ---------------------------------------------------------------------------
// Launch
// ---------------------------------------------------------------------------
extern "C" void kernel_launch(void* const* d_in, const int* in_sizes, int n_in,
                              void* d_out, int out_size)
{
    const float* z  = (const float*)d_in[0];
    const void*  ei = d_in[1];
    const float* W1 = (const float*)d_in[2];
    const float* b1 = (const float*)d_in[3];
    const float* W2 = (const float*)d_in[4];
    const float* b2 = (const float*)d_in[5];
    float* out = (float*)d_out;

    const int N = in_sizes[0] / D;   // 100000
    const int E = out_size;          // 800000

    cudaFuncSetAttribute(node_mma_kernel,
                         cudaFuncAttributeMaxDynamicSharedMemorySize, 52224);
    node_mma_kernel<<<296, 256, 52224>>>(z, W1, b1, N);

    edge_kernel<<<1184, 256>>>(ei, W2, b2, out, E, N);
}